// round 1
// baseline (speedup 1.0000x reference)
#include <cuda_runtime.h>
#include <cstdint>

// ---------------------------------------------------------------------------
// BLNN: Legendre transform of an ICNN via damped fixed-point iteration.
//   per-row gradient is independent; only coupling is the global mean-norm
//   early-stop. Persistent kernel, 128 CTAs (1/SM), 8 rows/CTA (1 warp/row).
//   Weights live in smem with stride-129 padding (conflict-free fwd+bwd).
//   Early-stop is synchronized with per-iteration fixed-point atomics; the
//   wait for iteration i-1's verdict happens AFTER computing g_i, so the
//   reduction latency hides behind compute.
// ---------------------------------------------------------------------------

#define NCTA        128
#define ROWS_PER_CTA  8
#define MAX_IT      500
// mean(norm) < 0.001  <=>  sum(norm) < 0.001*1024 ; fixed-point scale 2^32
#define ERR_THRESH  4398046511ULL   // 0.001 * 1024 * 2^32

__device__ unsigned long long g_err[MAX_IT];
__device__ unsigned int       g_cnt[MAX_IT];

__global__ void blnn_init_kernel() {
    int i = blockIdx.x * blockDim.x + threadIdx.x;
    if (i < MAX_IT) { g_err[i] = 0ULL; g_cnt[i] = 0u; }
}

__device__ __forceinline__ float softplus_f(float x) {
    // stable: max(x,0) + log1p(exp(-|x|))
    return fmaxf(x, 0.0f) + log1pf(expf(-fabsf(x)));
}
__device__ __forceinline__ float sigmoid_f(float x) {
    return 1.0f / (1.0f + expf(-x));
}

// shared memory layout (floats)
//  wy0t [64][129]  wy0t[c*129+h] = Wy0[h][c]
//  wy1t [64][129]
//  wz1t [128][129] wz1t[k*129+j] = clip(Wz1)[j][k]
//  wy2s [64], wz2s [128] (clipped), by0s[128], by1s[128]
//  misc: [0]=by2, [1]=done flag (int), [2..9]=per-warp norms
//  rowbuf: 8 warps * 448 ( xs[64], h0s[128], d01[256] interleaved d1/d0 )
#define OFF_WY0T   0
#define OFF_WY1T   8256
#define OFF_WZ1T   16512
#define OFF_WY2    33024
#define OFF_WZ2    33088
#define OFF_BY0    33216
#define OFF_BY1    33344
#define OFF_MISC   33472
#define OFF_ROWBUF 33488
#define SMEM_FLOATS (OFF_ROWBUF + ROWS_PER_CTA * 448)
#define SMEM_BYTES  (SMEM_FLOATS * 4)

__global__ void __launch_bounds__(256, 1)
blnn_main_kernel(const float* __restrict__ x_in,
                 const float* __restrict__ Wy0, const float* __restrict__ by0,
                 const float* __restrict__ Wy1, const float* __restrict__ by1,
                 const float* __restrict__ Wz1,
                 const float* __restrict__ Wy2, const float* __restrict__ by2,
                 const float* __restrict__ Wz2,
                 float* __restrict__ out)
{
    extern __shared__ float sm[];
    float* wy0t = sm + OFF_WY0T;
    float* wy1t = sm + OFF_WY1T;
    float* wz1t = sm + OFF_WZ1T;
    float* wy2s = sm + OFF_WY2;
    float* wz2s = sm + OFF_WZ2;
    float* by0s = sm + OFF_BY0;
    float* by1s = sm + OFF_BY1;
    float* misc = sm + OFF_MISC;

    const int tid = threadIdx.x;
    const int w   = tid >> 5;
    const int l   = tid & 31;

    // ---- one-time weight staging (transposed, padded, clipped) ----
    for (int idx = tid; idx < 128 * 64; idx += 256) {
        int h = idx >> 6, c = idx & 63;
        wy0t[c * 129 + h] = Wy0[idx];
        wy1t[c * 129 + h] = Wy1[idx];
    }
    for (int idx = tid; idx < 128 * 128; idx += 256) {
        int j = idx >> 7, k = idx & 127;
        wz1t[k * 129 + j] = fmaxf(Wz1[idx], 0.0f);
    }
    if (tid < 64)  wy2s[tid] = Wy2[tid];
    if (tid < 128) wz2s[tid] = fmaxf(Wz2[tid], 0.0f);
    if (tid < 128) { by0s[tid] = by0[tid]; by1s[tid] = by1[tid]; }
    if (tid == 0)  { misc[0] = by2[0]; ((int*)misc)[1] = 0; }
    __syncthreads();

    const float by2v = misc[0];
    volatile int* doneFlag = ((volatile int*)misc) + 1;
    float* wnorm = misc + 2;

    const int row = blockIdx.x * ROWS_PER_CTA + w;
    float* xs  = sm + OFF_ROWBUF + w * 448;   // 64
    float* h0s = xs + 64;                     // 128
    float* d01 = xs + 192;                    // 256 : [2j]=d1[j], [2j+1]=d0[j]

    const float za = x_in[row * 64 + l];
    const float zb = x_in[row * 64 + l + 32];
    float xa = 1.0f, xb = 1.0f;
    xs[l] = xa; xs[l + 32] = xb;

    const float w2ya = wy2s[l], w2yb = wy2s[l + 32];
    float wz2k[4], by0k[4], by1k[4];
    #pragma unroll
    for (int k = 0; k < 4; k++) {
        wz2k[k] = wz2s[l + 32 * k];
        by0k[k] = by0s[l + 32 * k];
        by1k[k] = by1s[l + 32 * k];
    }
    __syncwarp();

    for (int it = 0; it < MAX_IT; ++it) {
        // ---- stage A: s0 = Wy0 x + b0 ; s1 partial = Wy1 x + b1 ; s2 part --
        float a0[4], a1[4];
        #pragma unroll
        for (int k = 0; k < 4; k++) { a0[k] = by0k[k]; a1[k] = by1k[k]; }
        float s2p = w2ya * xa + w2yb * xb;

        #pragma unroll 4
        for (int c = 0; c < 64; c++) {
            float xc = xs[c];
            const float* p0 = wy0t + c * 129 + l;
            const float* p1 = wy1t + c * 129 + l;
            #pragma unroll
            for (int k = 0; k < 4; k++) {
                a0[k] = fmaf(p0[32 * k], xc, a0[k]);
                a1[k] = fmaf(p1[32 * k], xc, a1[k]);
            }
        }
        float sg0[4];
        #pragma unroll
        for (int k = 0; k < 4; k++) {
            float h0v = softplus_f(a0[k]);
            sg0[k] = sigmoid_f(a0[k]);
            h0s[l + 32 * k] = h0v;
        }
        __syncwarp();

        // ---- stage B: s1 += Wz1c h0 ; h1, sig1, s2 ------------------------
        #pragma unroll 4
        for (int kp = 0; kp < 128; kp++) {
            float hv = h0s[kp];
            const float* pz = wz1t + kp * 129 + l;
            #pragma unroll
            for (int k = 0; k < 4; k++)
                a1[k] = fmaf(pz[32 * k], hv, a1[k]);
        }
        float d1k[4];
        #pragma unroll
        for (int k = 0; k < 4; k++) {
            float h1v = softplus_f(a1[k]);
            float sg1 = sigmoid_f(a1[k]);
            s2p = fmaf(wz2k[k], h1v, s2p);
            d1k[k] = wz2k[k] * sg1;
        }
        #pragma unroll
        for (int off = 16; off > 0; off >>= 1)
            s2p += __shfl_xor_sync(0xffffffffu, s2p, off);
        float sg2 = sigmoid_f(s2p + by2v);
        #pragma unroll
        for (int k = 0; k < 4; k++) {
            d1k[k] *= sg2;
            d01[2 * (l + 32 * k)] = d1k[k];
        }
        __syncwarp();

        // ---- stage C: d0 = sig(s0) * (Wz1c^T d1) --------------------------
        float b0acc[4];
        #pragma unroll
        for (int k = 0; k < 4; k++) b0acc[k] = 0.0f;
        #pragma unroll 4
        for (int j = 0; j < 128; j++) {
            float dv = d01[2 * j];
            #pragma unroll
            for (int k = 0; k < 4; k++)
                b0acc[k] = fmaf(wz1t[(l + 32 * k) * 129 + j], dv, b0acc[k]);
        }
        #pragma unroll
        for (int k = 0; k < 4; k++)
            d01[2 * (l + 32 * k) + 1] = sg0[k] * b0acc[k];
        __syncwarp();

        // ---- stage D: g = sg2*Wy2 + Wy1^T d1 + Wy0^T d0 + x1 --------------
        float gA = fmaf(sg2, w2ya, xa);
        float gB = fmaf(sg2, w2yb, xb);
        #pragma unroll 2
        for (int j = 0; j < 128; j++) {
            float2 dd = *(const float2*)(d01 + 2 * j);
            gA = fmaf(dd.x, wy1t[l * 129 + j], gA);
            gA = fmaf(dd.y, wy0t[l * 129 + j], gA);
            gB = fmaf(dd.x, wy1t[(l + 32) * 129 + j], gB);
            gB = fmaf(dd.y, wy0t[(l + 32) * 129 + j], gB);
        }
        float ra = za - gA;
        float rb = zb - gB;
        float n2 = ra * ra + rb * rb;
        #pragma unroll
        for (int off = 16; off > 0; off >>= 1)
            n2 += __shfl_xor_sync(0xffffffffu, n2, off);
        if (l == 0) wnorm[w] = sqrtf(n2);
        __syncthreads();

        // ---- convergence protocol (thread 0) ------------------------------
        if (tid == 0) {
            int d = *doneFlag;
            if (it > 0 && !d) {
                volatile unsigned int* pc = &g_cnt[it - 1];
                while (*pc < (unsigned)NCTA) { /* spin; cheap, usually done */ }
                __threadfence();
                unsigned long long e =
                    *(volatile unsigned long long*)&g_err[it - 1];
                if (e < ERR_THRESH) { d = 1; *doneFlag = 1; }
            }
            if (!d) {
                float s = 0.0f;
                #pragma unroll
                for (int q = 0; q < ROWS_PER_CTA; q++) s += wnorm[q];
                atomicAdd(&g_err[it],
                          (unsigned long long)((double)s * 4294967296.0));
                __threadfence();
                atomicAdd(&g_cnt[it], 1u);
            }
        }
        __syncthreads();
        if (*doneFlag) break;   // uniform across CTAs (same global data)

        // ---- update (reference: gated by done from iteration it-1) -------
        float lr = 2.0f / ((float)it + 1.0f);
        xa = fmaf(lr, ra, xa);
        xb = fmaf(lr, rb, xb);
        xs[l] = xa; xs[l + 32] = xb;
        __syncwarp();
    }

    // output: x1 + CONVEX * z, CONVEX = 1
    out[row * 64 + l]      = xa + za;
    out[row * 64 + l + 32] = xb + zb;
}

extern "C" void kernel_launch(void* const* d_in, const int* in_sizes, int n_in,
                              void* d_out, int out_size) {
    const float* x   = (const float*)d_in[0];
    const float* Wy0 = (const float*)d_in[1];
    const float* by0 = (const float*)d_in[2];
    const float* Wy1 = (const float*)d_in[3];
    const float* by1 = (const float*)d_in[4];
    const float* Wz1 = (const float*)d_in[5];
    const float* Wy2 = (const float*)d_in[6];
    const float* by2 = (const float*)d_in[7];
    const float* Wz2 = (const float*)d_in[8];
    float* out = (float*)d_out;

    static bool attr_set = false;
    if (!attr_set) {
        cudaFuncSetAttribute(blnn_main_kernel,
                             cudaFuncAttributeMaxDynamicSharedMemorySize,
                             SMEM_BYTES);
        attr_set = true;
    }

    blnn_init_kernel<<<2, 256>>>();
    blnn_main_kernel<<<NCTA, 256, SMEM_BYTES>>>(x, Wy0, by0, Wy1, by1, Wz1,
                                                Wy2, by2, Wz2, out);
}

// round 2
// speedup vs baseline: 1.1650x; 1.1650x over previous
#include <cuda_runtime.h>
#include <cstdint>

// ---------------------------------------------------------------------------
// BLNN round 2: 2-warp teams x 2 rows -> every smem weight load feeds 2 rows.
//  - packA [c][lane64][4]  = {Wy0[h0][c],Wy0[h1][c],Wy1[h0][c],Wy1[h1][c]} (LDS.128)
//  - packD [j2][c][4]      = {Wy1[2j2][c],Wy0[2j2][c],Wy1[2j2+1][c],Wy0[2j2+1][c]}
//  - wz1t stride-129 single copy serves fwd (stage B) and bwd (stage C)
//  - activation broadcasts packed float2/float4 (both rows, one wavefront)
// ---------------------------------------------------------------------------

#define NCTA        128
#define MAX_IT      500
// mean(norm) < 0.001  <=>  sum(norm) < 0.001*1024 ; fixed-point scale 2^32
#define ERR_THRESH  4398046511ULL

__device__ unsigned long long g_err[MAX_IT];
__device__ unsigned int       g_cnt[MAX_IT];

__global__ void blnn_init_kernel() {
    int i = blockIdx.x * blockDim.x + threadIdx.x;
    if (i < MAX_IT) { g_err[i] = 0ULL; g_cnt[i] = 0u; }
}

__device__ __forceinline__ float softplus_f(float x) {
    return fmaxf(x, 0.0f) + log1pf(expf(-fabsf(x)));
}
__device__ __forceinline__ float sigmoid_f(float x) {
    return 1.0f / (1.0f + expf(-x));
}

// ---- shared layout (float offsets) ----
#define OFF_WZ1T   0        // 128*129
#define OFF_PACKA  16512    // 16384
#define OFF_PACKD  32896    // 16384
#define OFF_WY2    49280    // 64
#define OFF_WZ2    49344    // 128
#define OFF_BY0    49472    // 128
#define OFF_BY1    49600    // 128
#define OFF_MISC   49728    // 16  [0]=by2 [1]=done
#define OFF_NRM    49744    // 16
#define OFF_S2W    49760    // 16
#define OFF_TEAM   49776    // 4 teams * 1152
// per-team: xboth f2[64] @0, h0b f2[128] @128, d1b f2[128] @384,
//           dr0 f[256] @640, dr1 f[256] @896   (total 1152)
#define SMEM_FLOATS (OFF_TEAM + 4 * 1152)
#define SMEM_BYTES  (SMEM_FLOATS * 4)

__global__ void __launch_bounds__(256, 1)
blnn_main_kernel(const float* __restrict__ x_in,
                 const float* __restrict__ Wy0, const float* __restrict__ by0,
                 const float* __restrict__ Wy1, const float* __restrict__ by1,
                 const float* __restrict__ Wz1,
                 const float* __restrict__ Wy2, const float* __restrict__ by2,
                 const float* __restrict__ Wz2,
                 float* __restrict__ out)
{
    extern __shared__ float sm[];
    float* wz1t = sm + OFF_WZ1T;
    float* wy2s = sm + OFF_WY2;
    float* wz2s = sm + OFF_WZ2;
    float* by0s = sm + OFF_BY0;
    float* by1s = sm + OFF_BY1;
    float* misc = sm + OFF_MISC;
    float* nrm  = sm + OFF_NRM;
    float* s2w  = sm + OFF_S2W;

    const int tid    = threadIdx.x;
    const int l      = tid & 31;
    const int t      = (tid >> 5) & 1;
    const int team   = tid >> 6;
    const int lane64 = tid & 63;

    // ---- one-time staging ----
    for (int idx = tid; idx < 128 * 128; idx += 256) {
        int j = idx >> 7, k = idx & 127;
        wz1t[k * 129 + j] = fmaxf(Wz1[idx], 0.0f);
    }
    for (int idx = tid; idx < 4096; idx += 256) {
        int c = idx >> 6, ln = idx & 63;
        int tt = ln >> 5, ll = ln & 31;
        int h0 = 64 * tt + ll, h1 = h0 + 32;
        float4 v;
        v.x = Wy0[h0 * 64 + c]; v.y = Wy0[h1 * 64 + c];
        v.z = Wy1[h0 * 64 + c]; v.w = Wy1[h1 * 64 + c];
        ((float4*)(sm + OFF_PACKA))[idx] = v;
    }
    for (int idx = tid; idx < 4096; idx += 256) {
        int j2 = idx >> 6, c = idx & 63;
        float4 v;
        v.x = Wy1[(2 * j2) * 64 + c];     v.y = Wy0[(2 * j2) * 64 + c];
        v.z = Wy1[(2 * j2 + 1) * 64 + c]; v.w = Wy0[(2 * j2 + 1) * 64 + c];
        ((float4*)(sm + OFF_PACKD))[idx] = v;
    }
    if (tid < 64)  wy2s[tid] = Wy2[tid];
    if (tid < 128) {
        wz2s[tid] = fmaxf(Wz2[tid], 0.0f);
        by0s[tid] = by0[tid];
        by1s[tid] = by1[tid];
    }
    if (tid == 0) { misc[0] = by2[0]; ((int*)misc)[1] = 0; }

    const int h0i  = 64 * t + l;
    const int h1i  = h0i + 32;
    const int c_own = lane64;
    const int r0   = blockIdx.x * 8 + team * 2;

    float* tb = sm + OFF_TEAM + team * 1152;
    float2* xboth = (float2*)tb;            // [64]
    float2* h0b   = (float2*)(tb + 128);    // [128]
    float2* d1b   = (float2*)(tb + 384);    // [128]
    float*  dr0   = tb + 640;               // [256] interleaved d1/d0 row0
    float*  dr1   = tb + 896;               // [256] row1
    const float4* packA4 = (const float4*)(sm + OFF_PACKA);
    const float4* packD4 = (const float4*)(sm + OFF_PACKD);
    const float4* dr0_4  = (const float4*)dr0;
    const float4* dr1_4  = (const float4*)dr1;

    const float z0 = x_in[r0 * 64 + c_own];
    const float z1 = x_in[(r0 + 1) * 64 + c_own];
    float x0 = 1.0f, x1v = 1.0f;
    xboth[c_own] = make_float2(1.0f, 1.0f);
    __syncthreads();

    const float by2v  = misc[0];
    const float wy2c  = wy2s[c_own];
    const float wz2h0 = wz2s[h0i], wz2h1 = wz2s[h1i];
    const float b0h0  = by0s[h0i], b0h1 = by0s[h1i];
    const float b1h0  = by1s[h0i], b1h1 = by1s[h1i];
    volatile int* doneFlag = ((volatile int*)misc) + 1;

    for (int it = 0; it < MAX_IT; ++it) {
        // ---- stage A: a0/a1 = Wy{0,1} x + b (2 h x 2 rows) ----------------
        float A00 = b0h0, A01 = b0h0, A10 = b0h1, A11 = b0h1;
        float S00 = b1h0, S01 = b1h0, S10 = b1h1, S11 = b1h1;
        #pragma unroll 4
        for (int c = 0; c < 64; c++) {
            float4 wv = packA4[c * 64 + lane64];
            float2 xc = xboth[c];
            A00 = fmaf(wv.x, xc.x, A00); A01 = fmaf(wv.x, xc.y, A01);
            A10 = fmaf(wv.y, xc.x, A10); A11 = fmaf(wv.y, xc.y, A11);
            S00 = fmaf(wv.z, xc.x, S00); S01 = fmaf(wv.z, xc.y, S01);
            S10 = fmaf(wv.w, xc.x, S10); S11 = fmaf(wv.w, xc.y, S11);
        }
        float sg0_00 = sigmoid_f(A00), sg0_01 = sigmoid_f(A01);
        float sg0_10 = sigmoid_f(A10), sg0_11 = sigmoid_f(A11);
        h0b[h0i] = make_float2(softplus_f(A00), softplus_f(A01));
        h0b[h1i] = make_float2(softplus_f(A10), softplus_f(A11));
        __syncthreads();

        // ---- stage B: s1 += Wz1c h0 ---------------------------------------
        {
            const float* pz = wz1t + h0i;
            #pragma unroll 4
            for (int kp = 0; kp < 128; kp++) {
                float  w0 = pz[kp * 129];
                float  w1 = pz[kp * 129 + 32];
                float2 hv = h0b[kp];
                S00 = fmaf(w0, hv.x, S00); S01 = fmaf(w0, hv.y, S01);
                S10 = fmaf(w1, hv.x, S10); S11 = fmaf(w1, hv.y, S11);
            }
        }
        float h1_00 = softplus_f(S00), h1_01 = softplus_f(S01);
        float h1_10 = softplus_f(S10), h1_11 = softplus_f(S11);
        float s2p0 = fmaf(wy2c, x0,  fmaf(wz2h0, h1_00, wz2h1 * h1_10));
        float s2p1 = fmaf(wy2c, x1v, fmaf(wz2h0, h1_01, wz2h1 * h1_11));
        #pragma unroll
        for (int off = 16; off > 0; off >>= 1) {
            s2p0 += __shfl_xor_sync(0xffffffffu, s2p0, off);
            s2p1 += __shfl_xor_sync(0xffffffffu, s2p1, off);
        }
        if (l == 0) {
            s2w[(team * 2 + t) * 2 + 0] = s2p0;
            s2w[(team * 2 + t) * 2 + 1] = s2p1;
        }
        __syncthreads();
        float sg2_0 = sigmoid_f(s2w[team * 4 + 0] + s2w[team * 4 + 2] + by2v);
        float sg2_1 = sigmoid_f(s2w[team * 4 + 1] + s2w[team * 4 + 3] + by2v);
        float d1_00 = wz2h0 * sigmoid_f(S00) * sg2_0;
        float d1_01 = wz2h0 * sigmoid_f(S01) * sg2_1;
        float d1_10 = wz2h1 * sigmoid_f(S10) * sg2_0;
        float d1_11 = wz2h1 * sigmoid_f(S11) * sg2_1;
        d1b[h0i] = make_float2(d1_00, d1_01);
        d1b[h1i] = make_float2(d1_10, d1_11);
        dr0[2 * h0i] = d1_00; dr0[2 * h1i] = d1_10;
        dr1[2 * h0i] = d1_01; dr1[2 * h1i] = d1_11;
        __syncthreads();

        // ---- stage C: d0 = sg0 * (Wz1c^T d1) ------------------------------
        float C00 = 0.0f, C01 = 0.0f, C10 = 0.0f, C11 = 0.0f;
        {
            const float* p0 = wz1t + h0i * 129;
            const float* p1 = wz1t + h1i * 129;
            #pragma unroll 4
            for (int j = 0; j < 128; j++) {
                float2 dv = d1b[j];
                float  w0 = p0[j], w1 = p1[j];
                C00 = fmaf(w0, dv.x, C00); C01 = fmaf(w0, dv.y, C01);
                C10 = fmaf(w1, dv.x, C10); C11 = fmaf(w1, dv.y, C11);
            }
        }
        dr0[2 * h0i + 1] = sg0_00 * C00; dr0[2 * h1i + 1] = sg0_10 * C10;
        dr1[2 * h0i + 1] = sg0_01 * C01; dr1[2 * h1i + 1] = sg0_11 * C11;
        __syncthreads();

        // ---- stage D: g = x1 + sg2*Wy2 + Wy1^T d1 + Wy0^T d0 --------------
        float g0a = 0.0f, g0b = 0.0f, g1a = 0.0f, g1b = 0.0f;
        #pragma unroll 2
        for (int j2 = 0; j2 < 64; j2++) {
            float4 wv = packD4[j2 * 64 + lane64];
            float4 dA = dr0_4[j2];
            float4 dB = dr1_4[j2];
            g0a = fmaf(wv.x, dA.x, g0a); g0b = fmaf(wv.y, dA.y, g0b);
            g0a = fmaf(wv.z, dA.z, g0a); g0b = fmaf(wv.w, dA.w, g0b);
            g1a = fmaf(wv.x, dB.x, g1a); g1b = fmaf(wv.y, dB.y, g1b);
            g1a = fmaf(wv.z, dB.z, g1a); g1b = fmaf(wv.w, dB.w, g1b);
        }
        float g0 = fmaf(sg2_0, wy2c, x0)  + g0a + g0b;
        float g1 = fmaf(sg2_1, wy2c, x1v) + g1a + g1b;

        float rv0 = z0 - g0;
        float rv1 = z1 - g1;
        float n0 = rv0 * rv0, n1 = rv1 * rv1;
        #pragma unroll
        for (int off = 16; off > 0; off >>= 1) {
            n0 += __shfl_xor_sync(0xffffffffu, n0, off);
            n1 += __shfl_xor_sync(0xffffffffu, n1, off);
        }
        if (l == 0) {
            nrm[(team * 2 + t) * 2 + 0] = n0;
            nrm[(team * 2 + t) * 2 + 1] = n1;
        }
        __syncthreads();

        // ---- convergence protocol (thread 0) ------------------------------
        if (tid == 0) {
            int d = *doneFlag;
            if (it > 0 && !d) {
                volatile unsigned int* pc = &g_cnt[it - 1];
                while (*pc < (unsigned)NCTA) { }
                __threadfence();
                unsigned long long e =
                    *(volatile unsigned long long*)&g_err[it - 1];
                if (e < ERR_THRESH) { d = 1; *doneFlag = 1; }
            }
            if (!d) {
                float s = 0.0f;
                #pragma unroll
                for (int q = 0; q < 4; q++) {
                    s += sqrtf(nrm[q * 4 + 0] + nrm[q * 4 + 2]);
                    s += sqrtf(nrm[q * 4 + 1] + nrm[q * 4 + 3]);
                }
                atomicAdd(&g_err[it],
                          (unsigned long long)((double)s * 4294967296.0));
                __threadfence();
                atomicAdd(&g_cnt[it], 1u);
            }
        }
        __syncthreads();
        if (*doneFlag) break;

        // ---- damped update -------------------------------------------------
        float lr = 2.0f / ((float)it + 1.0f);
        x0  = fmaf(lr, rv0, x0);
        x1v = fmaf(lr, rv1, x1v);
        xboth[c_own] = make_float2(x0, x1v);
        __syncthreads();
    }

    out[r0 * 64 + c_own]       = x0 + z0;
    out[(r0 + 1) * 64 + c_own] = x1v + z1;
}

extern "C" void kernel_launch(void* const* d_in, const int* in_sizes, int n_in,
                              void* d_out, int out_size) {
    const float* x   = (const float*)d_in[0];
    const float* Wy0 = (const float*)d_in[1];
    const float* by0 = (const float*)d_in[2];
    const float* Wy1 = (const float*)d_in[3];
    const float* by1 = (const float*)d_in[4];
    const float* Wz1 = (const float*)d_in[5];
    const float* Wy2 = (const float*)d_in[6];
    const float* by2 = (const float*)d_in[7];
    const float* Wz2 = (const float*)d_in[8];
    float* out = (float*)d_out;

    static bool attr_set = false;
    if (!attr_set) {
        cudaFuncSetAttribute(blnn_main_kernel,
                             cudaFuncAttributeMaxDynamicSharedMemorySize,
                             SMEM_BYTES);
        attr_set = true;
    }

    blnn_init_kernel<<<2, 256>>>();
    blnn_main_kernel<<<NCTA, 256, SMEM_BYTES>>>(x, Wy0, by0, Wy1, by1, Wz1,
                                                Wy2, by2, Wz2, out);
}

// round 3
// speedup vs baseline: 1.6289x; 1.3983x over previous
#include <cuda_runtime.h>
#include <cstdint>

// ---------------------------------------------------------------------------
// BLNN round 3: 512 threads/CTA = 16 warps/SM. 2 teams x (8 warps, 4 rows).
//  - Every weight load feeds 4 rows (float4 row-vector accumulators).
//  - Reduction dims (c / kp / j / h) split across thread-halves/quarters,
//    combined via one smem reduce per stage.
//  - All intra-loop syncs are team-scoped named barriers (bar.sync id,256).
//  - Convergence: one u64 atomic per team packing {count<<52 | err*2^32};
//    done(it-1) prefetched at loop top (LDG hides under stage A); exit
//    rolls back to x_old kept in registers.
//  - Single-copy weights, conflict-free in both directions:
//      wz1t[k*129+j] = clip(Wz1)[j][k]   (fwd: lanes-h stride1; bwd: stride129)
//      wyA  f2 [c*129+h] = {Wy0[h][c],Wy1[h][c]} (A: lanes-h stride1;
//                                                 D: lanes-c stride 258 words)
// ---------------------------------------------------------------------------

#define NCTA      128
#define THREADS   512
#define NTEAMS    256ULL
#define MAX_IT    500
#define CNT_SHIFT 52
#define ERR_MASK  ((1ULL << 52) - 1)
// sum(norm) < 0.001*1024 = 1.024 ; fixed-point scale 2^32
#define ERR_THRESH 4398046511ULL

__device__ unsigned long long g_stat[MAX_IT];

__global__ void blnn_init_kernel() {
    int i = blockIdx.x * blockDim.x + threadIdx.x;
    if (i < MAX_IT) g_stat[i] = 0ULL;
}

__device__ __forceinline__ float softplus_f(float x) {
    return fmaxf(x, 0.0f) + log1pf(expf(-fabsf(x)));
}
__device__ __forceinline__ float sigmoid_f(float x) {
    return 1.0f / (1.0f + expf(-x));
}
__device__ __forceinline__ float4 f4add(float4 a, float4 b) {
    return make_float4(a.x + b.x, a.y + b.y, a.z + b.z, a.w + b.w);
}
__device__ __forceinline__ void wred4(float4& v) {
    #pragma unroll
    for (int o = 16; o > 0; o >>= 1) {
        v.x += __shfl_xor_sync(0xffffffffu, v.x, o);
        v.y += __shfl_xor_sync(0xffffffffu, v.y, o);
        v.z += __shfl_xor_sync(0xffffffffu, v.z, o);
        v.w += __shfl_xor_sync(0xffffffffu, v.w, o);
    }
}

// ---- shared layout (float offsets) ----
#define OFF_WZ1T   0        // 128*129 = 16512
#define OFF_WYA    16512    // 64*129 float2 = 16512 floats
#define OFF_WY2V   33024    // 64
#define OFF_WZ2V   33088    // 128
#define OFF_BY0V   33216    // 128
#define OFF_BY1V   33344    // 128
#define OFF_MISC   33472    // 16 ([0]=by2)
#define OFF_TEAM   33488
#define TEAM_STRIDE 3648
// per-team (floats): xb4 @0(256) h0b4 @256(512) sg0b4 @768(512) d1b4 @1280(512)
//   d0b4 @1792(512) red4 @2304(512) gpart @2816(768) s2p @3584(16)
//   wyp @3600(8) nrm @3608(8) wy2x @3616(4) flags @3620(4)
#define SMEM_FLOATS (OFF_TEAM + 2 * TEAM_STRIDE)
#define SMEM_BYTES  (SMEM_FLOATS * 4)

#define TBAR() asm volatile("bar.sync %0, 256;" :: "r"(team + 1) : "memory")

__global__ void __launch_bounds__(THREADS, 1)
blnn_main_kernel(const float* __restrict__ x_in,
                 const float* __restrict__ Wy0, const float* __restrict__ by0,
                 const float* __restrict__ Wy1, const float* __restrict__ by1,
                 const float* __restrict__ Wz1,
                 const float* __restrict__ Wy2, const float* __restrict__ by2,
                 const float* __restrict__ Wz2,
                 float* __restrict__ out)
{
    extern __shared__ float sm[];
    float*  wz1t = sm + OFF_WZ1T;
    float2* wyA  = (float2*)(sm + OFF_WYA);
    float*  wy2v = sm + OFF_WY2V;
    float*  wz2v = sm + OFF_WZ2V;
    float*  by0v = sm + OFF_BY0V;
    float*  by1v = sm + OFF_BY1V;
    float*  misc = sm + OFF_MISC;

    const int tid  = threadIdx.x;
    const int team = tid >> 8;       // 0,1
    const int wt   = tid & 255;      // thread-in-team
    const int l    = wt & 31;
    const int wteam = wt >> 5;       // warp-in-team 0..7
    const int half = wt >> 7;        // 0,1 (warps 0-3 / 4-7)
    const int hh   = wt & 127;       // owned h for stages A,B,C
    const int c    = wt & 63;        // owned c for stage D
    const int q    = wt >> 6;        // 0..3 h-quarter for stage D

    float* tb = sm + OFF_TEAM + team * TEAM_STRIDE;
    float4* xb4   = (float4*)(tb + 0);
    float4* h0b4  = (float4*)(tb + 256);
    float4* sg0b4 = (float4*)(tb + 768);
    float4* d1b4  = (float4*)(tb + 1280);
    float4* d0b4  = (float4*)(tb + 1792);
    float4* red4  = (float4*)(tb + 2304);
    float4* gpart4= (float4*)(tb + 2816);
    float4* s2p4  = (float4*)(tb + 3584);
    float4* wyp4  = (float4*)(tb + 3600);
    float4* nrm4w = (float4*)(tb + 3608);
    float4* wy2x4 = (float4*)(tb + 3616);
    volatile int* flagsI = (volatile int*)(tb + 3620);

    // ---- one-time weight staging ----
    for (int idx = tid; idx < 128 * 128; idx += THREADS) {
        int j = idx >> 7, k = idx & 127;
        wz1t[k * 129 + j] = fmaxf(Wz1[idx], 0.0f);
    }
    for (int idx = tid; idx < 64 * 128; idx += THREADS) {
        int cc = idx >> 7, h = idx & 127;
        wyA[cc * 129 + h] = make_float2(Wy0[h * 64 + cc], Wy1[h * 64 + cc]);
    }
    if (tid < 64)  wy2v[tid] = Wy2[tid];
    if (tid < 128) {
        wz2v[tid] = fmaxf(Wz2[tid], 0.0f);
        by0v[tid] = by0[tid];
        by1v[tid] = by1[tid];
    }
    if (tid == 0) misc[0] = by2[0];

    const int r0 = blockIdx.x * 8 + team * 4;

    // q0 threads own column c for 4 rows
    float4 zv = make_float4(0, 0, 0, 0);
    float4 xcur = make_float4(1, 1, 1, 1);
    float4 xold = xcur;
    float  wy2c = 0.0f;
    if (q == 0) {
        zv.x = x_in[(r0 + 0) * 64 + c];
        zv.y = x_in[(r0 + 1) * 64 + c];
        zv.z = x_in[(r0 + 2) * 64 + c];
        zv.w = x_in[(r0 + 3) * 64 + c];
        xb4[c] = xcur;
    }
    __syncthreads();
    if (q == 0) wy2c = wy2v[c];

    // init wy2x = Wy2^T x  (x = 1)
    if (q == 0) {
        float4 p = make_float4(wy2c, wy2c, wy2c, wy2c);
        wred4(p);
        if (l == 0) wyp4[wteam] = p;   // wteam 0,1
    }
    __syncthreads();
    if (wt == 0) wy2x4[0] = f4add(wyp4[0], wyp4[1]);
    __syncthreads();

    const float by2v = misc[0];
    const float b0h = by0v[hh];
    const float b1h = by1v[hh];
    const float wz2h = wz2v[hh];

    bool fin = false;

    #pragma unroll 1
    for (int it = 0; it < MAX_IT; ++it) {
        // prefetch prior-iteration status (leader only); hides under stage A
        unsigned long long vstat = 0ULL;
        if (wt == 0 && it > 0) {
            asm volatile("ld.global.cg.u64 %0, [%1];"
                         : "=l"(vstat) : "l"(g_stat + (it - 1)));
        }

        // ---- stage A: A = Wy0 x + b0 (half-split over c), S gets Wy1 part --
        float4 A, S;
        if (!half) { A = make_float4(b0h, b0h, b0h, b0h);
                     S = make_float4(b1h, b1h, b1h, b1h); }
        else       { A = make_float4(0, 0, 0, 0);
                     S = make_float4(0, 0, 0, 0); }
        {
            const int c0 = half * 32;
            #pragma unroll 4
            for (int cc = 0; cc < 32; cc++) {
                float2 w  = wyA[(c0 + cc) * 129 + hh];
                float4 xc = xb4[c0 + cc];
                A.x = fmaf(w.x, xc.x, A.x); A.y = fmaf(w.x, xc.y, A.y);
                A.z = fmaf(w.x, xc.z, A.z); A.w = fmaf(w.x, xc.w, A.w);
                S.x = fmaf(w.y, xc.x, S.x); S.y = fmaf(w.y, xc.y, S.y);
                S.z = fmaf(w.y, xc.z, S.z); S.w = fmaf(w.y, xc.w, S.w);
            }
        }
        if (half) red4[hh] = A;
        TBAR();
        if (!half) {
            float4 Af = f4add(A, red4[hh]);
            h0b4[hh]  = make_float4(softplus_f(Af.x), softplus_f(Af.y),
                                    softplus_f(Af.z), softplus_f(Af.w));
            sg0b4[hh] = make_float4(sigmoid_f(Af.x), sigmoid_f(Af.y),
                                    sigmoid_f(Af.z), sigmoid_f(Af.w));
        }
        TBAR();

        // ---- stage B: S += Wz1c h0 (half-split over kp) --------------------
        {
            const int k0 = half * 64;
            #pragma unroll 4
            for (int kk = 0; kk < 64; kk++) {
                float  w  = wz1t[(k0 + kk) * 129 + hh];
                float4 hv = h0b4[k0 + kk];
                S.x = fmaf(w, hv.x, S.x); S.y = fmaf(w, hv.y, S.y);
                S.z = fmaf(w, hv.z, S.z); S.w = fmaf(w, hv.w, S.w);
            }
        }
        if (half) red4[hh] = S;
        TBAR();
        float4 d1pre = make_float4(0, 0, 0, 0);
        float4 sg2v  = make_float4(0, 0, 0, 0);
        if (!half) {
            float4 Sf = f4add(S, red4[hh]);
            float4 h1 = make_float4(softplus_f(Sf.x), softplus_f(Sf.y),
                                    softplus_f(Sf.z), softplus_f(Sf.w));
            float4 sg1 = make_float4(sigmoid_f(Sf.x), sigmoid_f(Sf.y),
                                     sigmoid_f(Sf.z), sigmoid_f(Sf.w));
            float4 s2c = make_float4(wz2h * h1.x, wz2h * h1.y,
                                     wz2h * h1.z, wz2h * h1.w);
            wred4(s2c);
            if (l == 0) s2p4[wteam] = s2c;   // warps 0..3
            d1pre = make_float4(wz2h * sg1.x, wz2h * sg1.y,
                                wz2h * sg1.z, wz2h * sg1.w);
        }
        TBAR();
        if (!half) {
            float4 s2s = f4add(f4add(s2p4[0], s2p4[1]),
                               f4add(s2p4[2], s2p4[3]));
            float4 wx = wy2x4[0];
            sg2v = make_float4(sigmoid_f(s2s.x + wx.x + by2v),
                               sigmoid_f(s2s.y + wx.y + by2v),
                               sigmoid_f(s2s.z + wx.z + by2v),
                               sigmoid_f(s2s.w + wx.w + by2v));
            d1b4[hh] = make_float4(d1pre.x * sg2v.x, d1pre.y * sg2v.y,
                                   d1pre.z * sg2v.z, d1pre.w * sg2v.w);
        }
        TBAR();

        // ---- stage C: d0 = sg0 * (Wz1c^T d1) (half-split over j) ----------
        float4 C = make_float4(0, 0, 0, 0);
        {
            const int j0 = half * 64;
            const float* pz = wz1t + hh * 129 + j0;
            #pragma unroll 4
            for (int jj = 0; jj < 64; jj++) {
                float  w  = pz[jj];
                float4 dv = d1b4[j0 + jj];
                C.x = fmaf(w, dv.x, C.x); C.y = fmaf(w, dv.y, C.y);
                C.z = fmaf(w, dv.z, C.z); C.w = fmaf(w, dv.w, C.w);
            }
        }
        if (half) red4[hh] = C;
        TBAR();
        if (!half) {
            float4 Cf = f4add(C, red4[hh]);
            float4 s0 = sg0b4[hh];
            d0b4[hh] = make_float4(s0.x * Cf.x, s0.y * Cf.y,
                                   s0.z * Cf.z, s0.w * Cf.w);
        }
        TBAR();

        // ---- stage D: g = Wy1^T d1 + Wy0^T d0 (quarter-split over h) ------
        float4 g = make_float4(0, 0, 0, 0);
        {
            const int hq = 32 * q;
            #pragma unroll 4
            for (int h2 = 0; h2 < 32; h2++) {
                int    h  = hq + h2;
                float2 w2 = wyA[c * 129 + h];
                float4 d1 = d1b4[h];
                float4 d0 = d0b4[h];
                g.x = fmaf(w2.y, d1.x, g.x); g.x = fmaf(w2.x, d0.x, g.x);
                g.y = fmaf(w2.y, d1.y, g.y); g.y = fmaf(w2.x, d0.y, g.y);
                g.z = fmaf(w2.y, d1.z, g.z); g.z = fmaf(w2.x, d0.z, g.z);
                g.w = fmaf(w2.y, d1.w, g.w); g.w = fmaf(w2.x, d0.w, g.w);
            }
        }
        if (q) gpart4[(q - 1) * 64 + c] = g;
        TBAR();
        float4 rv = make_float4(0, 0, 0, 0);
        if (q == 0) {
            float4 gf = f4add(f4add(g, gpart4[c]),
                              f4add(gpart4[64 + c], gpart4[128 + c]));
            gf.x += xcur.x + sg2v.x * wy2c;
            gf.y += xcur.y + sg2v.y * wy2c;
            gf.z += xcur.z + sg2v.z * wy2c;
            gf.w += xcur.w + sg2v.w * wy2c;
            rv = make_float4(zv.x - gf.x, zv.y - gf.y,
                             zv.z - gf.z, zv.w - gf.w);
            float4 n = make_float4(rv.x * rv.x, rv.y * rv.y,
                                   rv.z * rv.z, rv.w * rv.w);
            wred4(n);
            if (l == 0) nrm4w[wteam] = n;    // wteam 0,1
            // tentative update (rollback via xold if done(it-1))
            xold = xcur;
            float lr = 2.0f / ((float)it + 1.0f);
            xcur.x = fmaf(lr, rv.x, xcur.x);
            xcur.y = fmaf(lr, rv.y, xcur.y);
            xcur.z = fmaf(lr, rv.z, xcur.z);
            xcur.w = fmaf(lr, rv.w, xcur.w);
            xb4[c] = xcur;
            float4 p = make_float4(wy2c * xcur.x, wy2c * xcur.y,
                                   wy2c * xcur.z, wy2c * xcur.w);
            wred4(p);
            if (l == 0) wyp4[wteam] = p;
        }
        TBAR();

        // ---- convergence protocol (team leader) ---------------------------
        if (wt == 0) {
            float4 ns = f4add(nrm4w[0], nrm4w[1]);
            float s = sqrtf(ns.x) + sqrtf(ns.y) + sqrtf(ns.z) + sqrtf(ns.w);
            atomicAdd(&g_stat[it],
                      (1ULL << CNT_SHIFT) +
                      (unsigned long long)((double)s * 4294967296.0));
            wy2x4[0] = f4add(wyp4[0], wyp4[1]);
            int dn = 0;
            if (it > 0) {
                while ((vstat >> CNT_SHIFT) < NTEAMS) {
                    asm volatile("ld.global.cg.u64 %0, [%1];"
                                 : "=l"(vstat) : "l"(g_stat + (it - 1)));
                }
                dn = (vstat & ERR_MASK) < ERR_THRESH;
            }
            flagsI[0] = dn;
        }
        TBAR();
        if (flagsI[0]) { fin = true; break; }
    }

    if (q == 0) {
        float4 xf = fin ? xold : xcur;
        out[(r0 + 0) * 64 + c] = xf.x + zv.x;
        out[(r0 + 1) * 64 + c] = xf.y + zv.y;
        out[(r0 + 2) * 64 + c] = xf.z + zv.z;
        out[(r0 + 3) * 64 + c] = xf.w + zv.w;
    }
}

extern "C" void kernel_launch(void* const* d_in, const int* in_sizes, int n_in,
                              void* d_out, int out_size) {
    const float* x   = (const float*)d_in[0];
    const float* Wy0 = (const float*)d_in[1];
    const float* by0 = (const float*)d_in[2];
    const float* Wy1 = (const float*)d_in[3];
    const float* by1 = (const float*)d_in[4];
    const float* Wz1 = (const float*)d_in[5];
    const float* Wy2 = (const float*)d_in[6];
    const float* by2 = (const float*)d_in[7];
    const float* Wz2 = (const float*)d_in[8];
    float* out = (float*)d_out;

    static bool attr_set = false;
    if (!attr_set) {
        cudaFuncSetAttribute(blnn_main_kernel,
                             cudaFuncAttributeMaxDynamicSharedMemorySize,
                             SMEM_BYTES);
        attr_set = true;
    }

    blnn_init_kernel<<<1, 512>>>();
    blnn_main_kernel<<<NCTA, THREADS, SMEM_BYTES>>>(x, Wy0, by0, Wy1, by1, Wz1,
                                                    Wy2, by2, Wz2, out);
}

// round 4
// speedup vs baseline: 1.7416x; 1.0691x over previous
#include <cuda_runtime.h>
#include <cstdint>

// ---------------------------------------------------------------------------
// BLNN round 4: one team per CTA — 16 warps cooperate on 8 rows.
//  Every weight load feeds 8 rows (float8 accumulators as float[8]).
//  Reductions: stages A/B/C split the contraction dim over 4 thread-quarters,
//  stage D over 8 octs; one smem partial-combine per stage.
//  Weights single-copy, conflict-free BOTH directions:
//    wy0t/wy1t [c*129+h] : stage A lanes-h stride 1 ; stage D lanes-c stride 129
//    wz1t [k*129+j]      : stage B lanes-h stride 1 ; stage C lanes-h stride 129
//  x / z / xold live in smem. Fast-math activations (__expf/__logf/__fdividef).
//  Convergence: one u64 atomic per CTA {cnt<<52 | err_fix32}; prior-iteration
//  status prefetched at loop top so the LDG hides under stage A.
// ---------------------------------------------------------------------------

#define NCTA      128
#define THREADS   512
#define NUNITS    128ULL
#define MAX_IT    500
#define CNT_SHIFT 52
#define ERR_MASK  ((1ULL << 52) - 1)
// sum(norm) < 0.001*1024 = 1.024 ; fixed-point scale 2^32
#define ERR_THRESH 4398046511ULL

__device__ unsigned long long g_stat[MAX_IT];

__global__ void blnn_init_kernel() {
    int i = blockIdx.x * blockDim.x + threadIdx.x;
    if (i < MAX_IT) g_stat[i] = 0ULL;
}

__device__ __forceinline__ float softplus_f(float x) {
    return fmaxf(x, 0.0f) + __logf(1.0f + __expf(-fabsf(x)));
}
__device__ __forceinline__ float sigmoid_f(float x) {
    return __fdividef(1.0f, 1.0f + __expf(-x));
}

// ---- shared layout (float offsets) ----
#define OFF_WZ1T  0        // 16512
#define OFF_WY0T  16512    // 8256
#define OFF_WY1T  24768    // 8256
#define OFF_WY2V  33024    // 64
#define OFF_WZ2V  33088    // 128
#define OFF_BY0V  33216    // 128
#define OFF_BY1V  33344    // 128
#define OFF_XB    33472    // 512  [64][8]
#define OFF_XOLD  33984    // 512
#define OFF_ZB    34496    // 512
#define OFF_H0B   35008    // 1024 [128][8]
#define OFF_SG0B  36032    // 1024
#define OFF_D1B   37056    // 1024
#define OFF_D0B   38080    // 1024
#define OFF_RED   39104    // 3584 (7*64*8; stages A/B/C use 3*128*8=3072)
#define OFF_S2P   42688    // 32  (4 warps x 8)
#define OFF_NRMP  42720    // 16  (2 x 8)
#define OFF_WYP   42736    // 16  (2 x 8)
#define OFF_SG2S  42752    // 8
#define OFF_WY2X  42760    // 8
#define OFF_MISC  42768    // 16  [0]=by2, int[1]=flag
#define SMEM_FLOATS 42784
#define SMEM_BYTES  (SMEM_FLOATS * 4)

#define LD8(dst, base) do { \
    float4 _a = *(const float4*)(base); \
    float4 _b = *(const float4*)((base) + 4); \
    dst[0]=_a.x; dst[1]=_a.y; dst[2]=_a.z; dst[3]=_a.w; \
    dst[4]=_b.x; dst[5]=_b.y; dst[6]=_b.z; dst[7]=_b.w; } while(0)
#define ST8(base, src) do { \
    *(float4*)(base)     = make_float4(src[0],src[1],src[2],src[3]); \
    *(float4*)((base)+4) = make_float4(src[4],src[5],src[6],src[7]); } while(0)

__global__ void __launch_bounds__(THREADS, 1)
blnn_main_kernel(const float* __restrict__ x_in,
                 const float* __restrict__ Wy0, const float* __restrict__ by0,
                 const float* __restrict__ Wy1, const float* __restrict__ by1,
                 const float* __restrict__ Wz1,
                 const float* __restrict__ Wy2, const float* __restrict__ by2,
                 const float* __restrict__ Wz2,
                 float* __restrict__ out)
{
    extern __shared__ float sm[];
    float* wz1t = sm + OFF_WZ1T;
    float* wy0t = sm + OFF_WY0T;
    float* wy1t = sm + OFF_WY1T;
    float* wy2v = sm + OFF_WY2V;
    float* wz2v = sm + OFF_WZ2V;
    float* by0v = sm + OFF_BY0V;
    float* by1v = sm + OFF_BY1V;
    float* xb   = sm + OFF_XB;
    float* xog  = sm + OFF_XOLD;
    float* zb   = sm + OFF_ZB;
    float* h0b  = sm + OFF_H0B;
    float* sg0b = sm + OFF_SG0B;
    float* d1b  = sm + OFF_D1B;
    float* d0b  = sm + OFF_D0B;
    float* red  = sm + OFF_RED;
    float* s2p  = sm + OFF_S2P;
    float* nrmp = sm + OFF_NRMP;
    float* wyp  = sm + OFF_WYP;
    float* sg2s = sm + OFF_SG2S;
    float* wy2x = sm + OFF_WY2X;
    float* misc = sm + OFF_MISC;
    volatile int* flagI = (volatile int*)(misc + 1);

    const int tid  = threadIdx.x;
    const int l    = tid & 31;
    const int warp = tid >> 5;
    const int qc   = tid >> 7;       // 0..3 reduction quarter (stages A,B,C)
    const int hh   = tid & 127;      // owned h (stages A,B,C)
    const int oc   = tid >> 6;       // 0..7 h-oct (stage D)
    const int c    = tid & 63;       // owned c (stage D)

    // ---- one-time staging ----
    for (int idx = tid; idx < 128 * 128; idx += THREADS) {
        int j = idx >> 7, k = idx & 127;
        wz1t[k * 129 + j] = fmaxf(Wz1[idx], 0.0f);
    }
    for (int idx = tid; idx < 64 * 128; idx += THREADS) {
        int cc = idx >> 7, h = idx & 127;
        wy0t[cc * 129 + h] = Wy0[h * 64 + cc];
        wy1t[cc * 129 + h] = Wy1[h * 64 + cc];
    }
    if (tid < 64)  wy2v[tid] = Wy2[tid];
    if (tid < 128) {
        wz2v[tid] = fmaxf(Wz2[tid], 0.0f);
        by0v[tid] = by0[tid];
        by1v[tid] = by1[tid];
    }
    const int r0 = blockIdx.x * 8;
    { // zb[c][r] = x_in[(r0+r)*64+c]; xb = 1
        int cc = tid >> 3, rr = tid & 7;
        zb[cc * 8 + rr] = x_in[(r0 + rr) * 64 + cc];
        xb[tid] = 1.0f;
    }
    if (tid == 0) {
        misc[0] = by2[0];
        *flagI = 0;
        float s = 0.0f;
        for (int i = 0; i < 64; i++) s += Wy2[i];
        #pragma unroll
        for (int r = 0; r < 8; r++) wy2x[r] = s;   // x = 1 initially
    }
    __syncthreads();

    const float by2v = misc[0];
    const float b0h  = (qc == 0) ? by0v[hh] : 0.0f;
    const float b1h  = (qc == 0) ? by1v[hh] : 0.0f;
    const float wz2h = wz2v[hh];

    bool fin = false;

    #pragma unroll 1
    for (int it = 0; it < MAX_IT; ++it) {
        unsigned long long vstat = 0ULL;
        if (tid == 0 && it > 0) {
            asm volatile("ld.global.cg.u64 %0, [%1];"
                         : "=l"(vstat) : "l"(g_stat + (it - 1)));
        }

        // ============ stage A: A = Wy0 x + b0 ; S = Wy1 x + b1 =============
        float A[8], S[8];
        #pragma unroll
        for (int r = 0; r < 8; r++) { A[r] = b0h; S[r] = b1h; }
        {
            const int c0 = qc * 16;
            #pragma unroll 4
            for (int cc = 0; cc < 16; cc++) {
                const int ci = c0 + cc;
                float w0 = wy0t[ci * 129 + hh];
                float w1 = wy1t[ci * 129 + hh];
                float xv[8]; LD8(xv, xb + ci * 8);
                #pragma unroll
                for (int r = 0; r < 8; r++) {
                    A[r] = fmaf(w0, xv[r], A[r]);
                    S[r] = fmaf(w1, xv[r], S[r]);
                }
            }
        }
        if (qc) ST8(red + (qc - 1) * 1024 + hh * 8, A);
        __syncthreads();
        if (!qc) {
            #pragma unroll
            for (int p = 0; p < 3; p++) {
                float t[8]; LD8(t, red + p * 1024 + hh * 8);
                #pragma unroll
                for (int r = 0; r < 8; r++) A[r] += t[r];
            }
            float h0[8], s0[8];
            #pragma unroll
            for (int r = 0; r < 8; r++) {
                h0[r] = softplus_f(A[r]);
                s0[r] = sigmoid_f(A[r]);
            }
            ST8(h0b + hh * 8, h0);
            ST8(sg0b + hh * 8, s0);
        }
        __syncthreads();

        // ============ stage B: S += Wz1c h0 ; h1/sg1/s2/sg2/d1 =============
        {
            const int k0 = qc * 32;
            #pragma unroll 4
            for (int kk = 0; kk < 32; kk++) {
                const int kp = k0 + kk;
                float w = wz1t[kp * 129 + hh];
                float hv[8]; LD8(hv, h0b + kp * 8);
                #pragma unroll
                for (int r = 0; r < 8; r++) S[r] = fmaf(w, hv[r], S[r]);
            }
        }
        if (qc) ST8(red + (qc - 1) * 1024 + hh * 8, S);
        __syncthreads();
        float d1pre[8];
        if (!qc) {
            #pragma unroll
            for (int p = 0; p < 3; p++) {
                float t[8]; LD8(t, red + p * 1024 + hh * 8);
                #pragma unroll
                for (int r = 0; r < 8; r++) S[r] += t[r];
            }
            float s2c[8];
            #pragma unroll
            for (int r = 0; r < 8; r++) {
                float h1 = softplus_f(S[r]);
                float sg1 = sigmoid_f(S[r]);
                s2c[r] = wz2h * h1;
                d1pre[r] = wz2h * sg1;
            }
            #pragma unroll
            for (int o = 16; o > 0; o >>= 1)
                #pragma unroll
                for (int r = 0; r < 8; r++)
                    s2c[r] += __shfl_xor_sync(0xffffffffu, s2c[r], o);
            if (l == 0) ST8(s2p + warp * 8, s2c);
        }
        __syncthreads();
        if (!qc) {
            float sg2[8];
            #pragma unroll
            for (int r = 0; r < 8; r++) {
                float s2s = s2p[r] + s2p[8 + r] + s2p[16 + r] + s2p[24 + r];
                sg2[r] = sigmoid_f(s2s + wy2x[r] + by2v);
                d1pre[r] *= sg2[r];
            }
            ST8(d1b + hh * 8, d1pre);
            if (tid == 0) ST8(sg2s, sg2);
        }
        __syncthreads();

        // ============ stage C: d0 = sg0 * (Wz1c^T d1) ======================
        float C[8];
        #pragma unroll
        for (int r = 0; r < 8; r++) C[r] = 0.0f;
        {
            const int j0 = qc * 32;
            const float* pz = wz1t + hh * 129 + j0;
            #pragma unroll 4
            for (int jj = 0; jj < 32; jj++) {
                float w = pz[jj];
                float dv[8]; LD8(dv, d1b + (j0 + jj) * 8);
                #pragma unroll
                for (int r = 0; r < 8; r++) C[r] = fmaf(w, dv[r], C[r]);
            }
        }
        if (qc) ST8(red + (qc - 1) * 1024 + hh * 8, C);
        __syncthreads();
        if (!qc) {
            #pragma unroll
            for (int p = 0; p < 3; p++) {
                float t[8]; LD8(t, red + p * 1024 + hh * 8);
                #pragma unroll
                for (int r = 0; r < 8; r++) C[r] += t[r];
            }
            float s0[8]; LD8(s0, sg0b + hh * 8);
            #pragma unroll
            for (int r = 0; r < 8; r++) C[r] *= s0[r];
            ST8(d0b + hh * 8, C);
        }
        __syncthreads();

        // ============ stage D: g = Wy1^T d1 + Wy0^T d0 (+x +sg2*Wy2) =======
        float g[8];
        #pragma unroll
        for (int r = 0; r < 8; r++) g[r] = 0.0f;
        {
            const int h0i = oc * 16;
            #pragma unroll 4
            for (int h2 = 0; h2 < 16; h2++) {
                const int h = h0i + h2;
                float w1 = wy1t[c * 129 + h];
                float w0 = wy0t[c * 129 + h];
                float dv1[8]; LD8(dv1, d1b + h * 8);
                float dv0[8]; LD8(dv0, d0b + h * 8);
                #pragma unroll
                for (int r = 0; r < 8; r++) {
                    g[r] = fmaf(w1, dv1[r], g[r]);
                    g[r] = fmaf(w0, dv0[r], g[r]);
                }
            }
        }
        if (oc) ST8(red + (oc - 1) * 512 + c * 8, g);
        __syncthreads();
        if (!oc) {
            #pragma unroll
            for (int p = 0; p < 7; p++) {
                float t[8]; LD8(t, red + p * 512 + c * 8);
                #pragma unroll
                for (int r = 0; r < 8; r++) g[r] += t[r];
            }
            float xc[8]; LD8(xc, xb + c * 8);
            float zv[8]; LD8(zv, zb + c * 8);
            float sg2[8]; LD8(sg2, sg2s);
            const float wy2c = wy2v[c];
            float rv[8], n[8], xn[8], p2[8];
            const float lr = 2.0f / ((float)it + 1.0f);
            #pragma unroll
            for (int r = 0; r < 8; r++) {
                float gf = g[r] + xc[r] + sg2[r] * wy2c;
                rv[r] = zv[r] - gf;
                n[r]  = rv[r] * rv[r];
                xn[r] = fmaf(lr, rv[r], xc[r]);
                p2[r] = wy2c * xn[r];
            }
            ST8(xog + c * 8, xc);
            ST8(xb + c * 8, xn);
            #pragma unroll
            for (int o = 16; o > 0; o >>= 1)
                #pragma unroll
                for (int r = 0; r < 8; r++) {
                    n[r]  += __shfl_xor_sync(0xffffffffu, n[r], o);
                    p2[r] += __shfl_xor_sync(0xffffffffu, p2[r], o);
                }
            if (l == 0) { ST8(nrmp + warp * 8, n); ST8(wyp + warp * 8, p2); }
        }
        __syncthreads();

        // ============ convergence protocol =================================
        if (tid == 0) {
            float s = 0.0f;
            #pragma unroll
            for (int r = 0; r < 8; r++) {
                s += sqrtf(nrmp[r] + nrmp[8 + r]);
                wy2x[r] = wyp[r] + wyp[8 + r];
            }
            atomicAdd(&g_stat[it],
                      (1ULL << CNT_SHIFT) +
                      (unsigned long long)((double)s * 4294967296.0));
            int dn = 0;
            if (it > 0) {
                while ((vstat >> CNT_SHIFT) < NUNITS) {
                    asm volatile("ld.global.cg.u64 %0, [%1];"
                                 : "=l"(vstat) : "l"(g_stat + (it - 1)));
                }
                dn = (vstat & ERR_MASK) < ERR_THRESH;
            }
            *flagI = dn;
        }
        __syncthreads();
        if (*flagI) { fin = true; break; }
    }

    if (!oc) {
        const float* xf = fin ? (xog + c * 8) : (xb + c * 8);
        #pragma unroll
        for (int r = 0; r < 8; r++)
            out[(r0 + r) * 64 + c] = xf[r] + zb[c * 8 + r];
    }
}

extern "C" void kernel_launch(void* const* d_in, const int* in_sizes, int n_in,
                              void* d_out, int out_size) {
    const float* x   = (const float*)d_in[0];
    const float* Wy0 = (const float*)d_in[1];
    const float* by0 = (const float*)d_in[2];
    const float* Wy1 = (const float*)d_in[3];
    const float* by1 = (const float*)d_in[4];
    const float* Wz1 = (const float*)d_in[5];
    const float* Wy2 = (const float*)d_in[6];
    const float* by2 = (const float*)d_in[7];
    const float* Wz2 = (const float*)d_in[8];
    float* out = (float*)d_out;

    static bool attr_set = false;
    if (!attr_set) {
        cudaFuncSetAttribute(blnn_main_kernel,
                             cudaFuncAttributeMaxDynamicSharedMemorySize,
                             SMEM_BYTES);
        attr_set = true;
    }

    blnn_init_kernel<<<1, 512>>>();
    blnn_main_kernel<<<NCTA, THREADS, SMEM_BYTES>>>(x, Wy0, by0, Wy1, by1, Wz1,
                                                    Wy2, by2, Wz2, out);
}

// round 5
// speedup vs baseline: 1.9750x; 1.1340x over previous
#include <cuda_runtime.h>
#include <cstdint>

// ---------------------------------------------------------------------------
// BLNN round 5: f32x2-packed FMA + distributed combines, no spills.
//  16 warps/CTA cooperate on 8 rows; accumulators are f32x2 (u64) pairs.
//  Stages A/B/C quarter-split over contraction dim, D oct-split; ALL quarters
//  store partials, then all 512 threads combine 2 of 1024 (h,row) outputs
//  each (consecutive-float loads, activations spread over all warps).
//  sg0 / sg2 persist in the consuming thread's registers across stages.
//  Weights single-copy, conflict-free both directions (stride-129 pads).
//  Convergence protocol unchanged from R4 (u64 atomic {cnt<<52|err}).
// ---------------------------------------------------------------------------

#define NCTA      128
#define THREADS   512
#define NUNITS    128ULL
#define MAX_IT    500
#define CNT_SHIFT 52
#define ERR_MASK  ((1ULL << 52) - 1)
#define ERR_THRESH 4398046511ULL   // 0.001*1024*2^32

typedef unsigned long long u64;

__device__ u64 g_stat[MAX_IT];

__global__ void blnn_init_kernel() {
    int i = blockIdx.x * blockDim.x + threadIdx.x;
    if (i < MAX_IT) g_stat[i] = 0ULL;
}

__device__ __forceinline__ u64 dup2(float w) {
    u64 r; asm("mov.b64 %0,{%1,%1};" : "=l"(r) : "f"(w)); return r;
}
__device__ __forceinline__ u64 fma2(u64 a, u64 b, u64 c) {
    u64 d; asm("fma.rn.f32x2 %0,%1,%2,%3;" : "=l"(d) : "l"(a), "l"(b), "l"(c));
    return d;
}
// softplus + sigmoid sharing one exp
__device__ __forceinline__ void act2(float a, float& sp, float& sg) {
    float e = __expf(-fabsf(a));
    float u = 1.0f + e;
    float r = __fdividef(1.0f, u);
    sp = fmaxf(a, 0.0f) + __logf(u);
    sg = (a >= 0.0f) ? r : e * r;
}

// ---- shared layout (float offsets) ----
#define OFF_WZ1T  0        // 16512
#define OFF_WY0T  16512    // 8256
#define OFF_WY1T  24768    // 8256
#define OFF_WY2V  33024    // 64
#define OFF_WZ2V  33088    // 128
#define OFF_BY0V  33216    // 128
#define OFF_BY1V  33344    // 128
#define OFF_XB    33472    // 512  [c*8+r]
#define OFF_XOLD  33984    // 512
#define OFF_ZB    34496    // 512
#define OFF_H0B   35008    // 1024 [h*8+r]
#define OFF_D1B   36032    // 1024
#define OFF_D0B   37056    // 1024
#define OFF_RED   38080    // 4096
#define OFF_S2P   42176    // 128 (16 warps x 8)
#define OFF_NRMP  42304    // 128
#define OFF_WYP   42432    // 128
#define OFF_WY2X  42560    // 8
#define OFF_MISC  42568    // 8  [0]=by2, int[1]=flag
#define SMEM_FLOATS 42576
#define SMEM_BYTES  (SMEM_FLOATS * 4)

__global__ void __launch_bounds__(THREADS, 1)
blnn_main_kernel(const float* __restrict__ x_in,
                 const float* __restrict__ Wy0, const float* __restrict__ by0,
                 const float* __restrict__ Wy1, const float* __restrict__ by1,
                 const float* __restrict__ Wz1,
                 const float* __restrict__ Wy2, const float* __restrict__ by2,
                 const float* __restrict__ Wz2,
                 float* __restrict__ out)
{
    extern __shared__ float sm[];
    float* wz1t = sm + OFF_WZ1T;
    float* wy0t = sm + OFF_WY0T;
    float* wy1t = sm + OFF_WY1T;
    float* wy2v = sm + OFF_WY2V;
    float* wz2v = sm + OFF_WZ2V;
    float* by0v = sm + OFF_BY0V;
    float* by1v = sm + OFF_BY1V;
    float* xb   = sm + OFF_XB;
    float* xog  = sm + OFF_XOLD;
    float* zb   = sm + OFF_ZB;
    float* h0b  = sm + OFF_H0B;
    float* d1b  = sm + OFF_D1B;
    float* d0b  = sm + OFF_D0B;
    float* red  = sm + OFF_RED;
    float* s2p  = sm + OFF_S2P;
    float* nrmp = sm + OFF_NRMP;
    float* wyp  = sm + OFF_WYP;
    float* wy2x = sm + OFF_WY2X;
    float* misc = sm + OFF_MISC;
    volatile int* flagI = (volatile int*)(misc + 1);

    const int tid  = threadIdx.x;
    const int l    = tid & 31;
    const int warp = tid >> 5;
    const int qc   = tid >> 7;       // stage A/B/C contraction quarter
    const int hh   = tid & 127;      // owned h in partial loops
    const int oc   = tid >> 6;       // stage D h-oct
    const int c    = tid & 63;       // owned c in stage D partial

    // ---- one-time staging ----
    for (int idx = tid; idx < 128 * 128; idx += THREADS) {
        int j = idx >> 7, k = idx & 127;
        wz1t[k * 129 + j] = fmaxf(Wz1[idx], 0.0f);
    }
    for (int idx = tid; idx < 64 * 128; idx += THREADS) {
        int cc = idx >> 7, h = idx & 127;
        wy0t[cc * 129 + h] = Wy0[h * 64 + cc];
        wy1t[cc * 129 + h] = Wy1[h * 64 + cc];
    }
    if (tid < 64)  wy2v[tid] = Wy2[tid];
    if (tid < 128) {
        wz2v[tid] = fmaxf(Wz2[tid], 0.0f);
        by0v[tid] = by0[tid];
        by1v[tid] = by1[tid];
    }
    const int r0 = blockIdx.x * 8;
    zb[tid] = x_in[(r0 + (tid & 7)) * 64 + (tid >> 3)];
    xb[tid] = 1.0f;
    if (tid == 0) { misc[0] = by2[0]; *flagI = 0; }
    __syncthreads();
    if (tid == 0) {
        float s = 0.0f;
        for (int i = 0; i < 64; i++) s += wy2v[i];
        #pragma unroll
        for (int r = 0; r < 8; r++) wy2x[r] = s;   // x = 1 initially
    }
    __syncthreads();

    const float by2v = misc[0];
    bool fin = false;

    #pragma unroll 1
    for (int it = 0; it < MAX_IT; ++it) {
        u64 vstat = 0ULL;
        if (tid == 0 && it > 0) {
            asm volatile("ld.global.cg.u64 %0, [%1];"
                         : "=l"(vstat) : "l"(g_stat + (it - 1)));
        }

        // ============ stage A partial: Wy0 x (A) and Wy1 x (S) =============
        u64 A0 = 0, A1 = 0, A2_ = 0, A3 = 0;
        u64 S0 = 0, S1 = 0, S2_ = 0, S3 = 0;
        {
            const float* pw0 = wy0t + qc * 16 * 129 + hh;
            const float* pw1 = wy1t + qc * 16 * 129 + hh;
            const ulonglong2* px = (const ulonglong2*)(xb + qc * 16 * 8);
            #pragma unroll 2
            for (int cc = 0; cc < 16; cc++) {
                u64 w0 = dup2(pw0[cc * 129]);
                u64 w1 = dup2(pw1[cc * 129]);
                ulonglong2 xlo = px[cc * 2];
                ulonglong2 xhi = px[cc * 2 + 1];
                A0 = fma2(w0, xlo.x, A0);  A1 = fma2(w0, xlo.y, A1);
                A2_ = fma2(w0, xhi.x, A2_); A3 = fma2(w0, xhi.y, A3);
                S0 = fma2(w1, xlo.x, S0);  S1 = fma2(w1, xlo.y, S1);
                S2_ = fma2(w1, xhi.x, S2_); S3 = fma2(w1, xhi.y, S3);
            }
        }
        {
            ulonglong2* pr = (ulonglong2*)(red + qc * 1024 + hh * 8);
            pr[0] = make_ulonglong2(A0, A1);
            pr[1] = make_ulonglong2(A2_, A3);
        }
        __syncthreads();

        // ---- A combine: each thread owns v=tid and v=tid+512 --------------
        float sg0a, sg0b_;
        {
            float a0 = red[tid] + red[1024 + tid] + red[2048 + tid] +
                       red[3072 + tid] + by0v[tid >> 3];
            float a1 = red[512 + tid] + red[1536 + tid] + red[2560 + tid] +
                       red[3584 + tid] + by0v[64 + (tid >> 3)];
            float h0a, h0bv;
            act2(a0, h0a, sg0a);
            act2(a1, h0bv, sg0b_);
            h0b[tid] = h0a;
            h0b[512 + tid] = h0bv;
        }
        __syncthreads();

        // ============ stage B partial: S += Wz1c h0 ========================
        {
            const float* pw = wz1t + qc * 32 * 129 + hh;
            const ulonglong2* ph = (const ulonglong2*)(h0b + qc * 32 * 8);
            #pragma unroll 4
            for (int kk = 0; kk < 32; kk++) {
                u64 w = dup2(pw[kk * 129]);
                ulonglong2 hlo = ph[kk * 2];
                ulonglong2 hhi = ph[kk * 2 + 1];
                S0 = fma2(w, hlo.x, S0);  S1 = fma2(w, hlo.y, S1);
                S2_ = fma2(w, hhi.x, S2_); S3 = fma2(w, hhi.y, S3);
            }
        }
        {
            ulonglong2* pr = (ulonglong2*)(red + qc * 1024 + hh * 8);
            pr[0] = make_ulonglong2(S0, S1);
            pr[1] = make_ulonglong2(S2_, S3);
        }
        __syncthreads();

        // ---- B combine: h1/sg1, s2 partial reduce --------------------------
        float sg2, d1a, d1bv;
        float wz2a, wz2b, sg1a, sg1b;
        {
            float s1a = red[tid] + red[1024 + tid] + red[2048 + tid] +
                        red[3072 + tid] + by1v[tid >> 3];
            float s1b = red[512 + tid] + red[1536 + tid] + red[2560 + tid] +
                        red[3584 + tid] + by1v[64 + (tid >> 3)];
            float h1a, h1b;
            act2(s1a, h1a, sg1a);
            act2(s1b, h1b, sg1b);
            wz2a = wz2v[tid >> 3];
            wz2b = wz2v[64 + (tid >> 3)];
            float s2c = wz2a * h1a + wz2b * h1b;
            s2c += __shfl_xor_sync(0xffffffffu, s2c, 8);
            s2c += __shfl_xor_sync(0xffffffffu, s2c, 16);
            if (l < 8) s2p[warp * 8 + l] = s2c;
        }
        __syncthreads();
        {
            float s2tot = 0.0f;
            #pragma unroll
            for (int w = 0; w < 16; w++) s2tot += s2p[w * 8 + (tid & 7)];
            float e = __expf(-(s2tot + wy2x[tid & 7] + by2v));
            sg2 = __fdividef(1.0f, 1.0f + e);
            d1a  = wz2a * sg1a * sg2;
            d1bv = wz2b * sg1b * sg2;
            d1b[tid] = d1a;
            d1b[512 + tid] = d1bv;
        }
        __syncthreads();

        // ============ stage C partial: Wz1c^T d1 ===========================
        {
            u64 C0 = 0, C1 = 0, C2_ = 0, C3 = 0;
            const float* pw = wz1t + hh * 129 + qc * 32;
            const ulonglong2* pd = (const ulonglong2*)(d1b + qc * 32 * 8);
            #pragma unroll 4
            for (int jj = 0; jj < 32; jj++) {
                u64 w = dup2(pw[jj]);
                ulonglong2 dlo = pd[jj * 2];
                ulonglong2 dhi = pd[jj * 2 + 1];
                C0 = fma2(w, dlo.x, C0);  C1 = fma2(w, dlo.y, C1);
                C2_ = fma2(w, dhi.x, C2_); C3 = fma2(w, dhi.y, C3);
            }
            ulonglong2* pr = (ulonglong2*)(red + qc * 1024 + hh * 8);
            pr[0] = make_ulonglong2(C0, C1);
            pr[1] = make_ulonglong2(C2_, C3);
        }
        __syncthreads();
        // ---- C combine: d0 = sg0 * sum ------------------------------------
        {
            float c0s = red[tid] + red[1024 + tid] + red[2048 + tid] +
                        red[3072 + tid];
            float c1s = red[512 + tid] + red[1536 + tid] + red[2560 + tid] +
                        red[3584 + tid];
            d0b[tid] = sg0a * c0s;
            d0b[512 + tid] = sg0b_ * c1s;
        }
        __syncthreads();

        // ============ stage D partial: Wy1^T d1 + Wy0^T d0 =================
        {
            u64 G0 = 0, G1 = 0, G2_ = 0, G3 = 0;
            const float* pw1 = wy1t + c * 129 + oc * 16;
            const float* pw0 = wy0t + c * 129 + oc * 16;
            const ulonglong2* pd1 = (const ulonglong2*)(d1b + oc * 16 * 8);
            const ulonglong2* pd0 = (const ulonglong2*)(d0b + oc * 16 * 8);
            #pragma unroll 2
            for (int h2 = 0; h2 < 16; h2++) {
                u64 w1 = dup2(pw1[h2]);
                u64 w0 = dup2(pw0[h2]);
                ulonglong2 alo = pd1[h2 * 2];
                ulonglong2 ahi = pd1[h2 * 2 + 1];
                ulonglong2 blo = pd0[h2 * 2];
                ulonglong2 bhi = pd0[h2 * 2 + 1];
                G0 = fma2(w1, alo.x, G0);  G1 = fma2(w1, alo.y, G1);
                G2_ = fma2(w1, ahi.x, G2_); G3 = fma2(w1, ahi.y, G3);
                G0 = fma2(w0, blo.x, G0);  G1 = fma2(w0, blo.y, G1);
                G2_ = fma2(w0, bhi.x, G2_); G3 = fma2(w0, bhi.y, G3);
            }
            ulonglong2* pr = (ulonglong2*)(red + oc * 512 + c * 8);
            pr[0] = make_ulonglong2(G0, G1);
            pr[1] = make_ulonglong2(G2_, G3);
        }
        __syncthreads();

        // ---- D combine: residual, update, norm partials --------------------
        {
            float gs = red[tid] + red[512 + tid] + red[1024 + tid] +
                       red[1536 + tid] + red[2048 + tid] + red[2560 + tid] +
                       red[3072 + tid] + red[3584 + tid];
            float xc = xb[tid];
            float zz = zb[tid];
            float wy2c = wy2v[tid >> 3];
            float gf = gs + xc + sg2 * wy2c;
            float rv = zz - gf;
            float nn = rv * rv;
            float lr = 2.0f / ((float)it + 1.0f);
            float xn = fmaf(lr, rv, xc);
            xog[tid] = xc;
            xb[tid] = xn;
            float p2 = wy2c * xn;
            nn += __shfl_xor_sync(0xffffffffu, nn, 8);
            nn += __shfl_xor_sync(0xffffffffu, nn, 16);
            p2 += __shfl_xor_sync(0xffffffffu, p2, 8);
            p2 += __shfl_xor_sync(0xffffffffu, p2, 16);
            if (l < 8) { nrmp[warp * 8 + l] = nn; wyp[warp * 8 + l] = p2; }
        }
        __syncthreads();

        // ============ convergence ==========================================
        if (tid < 8) {
            float nr = 0.0f, ws = 0.0f;
            #pragma unroll
            for (int w = 0; w < 16; w++) {
                nr += nrmp[w * 8 + tid];
                ws += wyp[w * 8 + tid];
            }
            wy2x[tid] = ws;
            float s = sqrtf(nr);
            s += __shfl_xor_sync(0xffu, s, 4, 8);
            s += __shfl_xor_sync(0xffu, s, 2, 8);
            s += __shfl_xor_sync(0xffu, s, 1, 8);
            if (tid == 0) {
                atomicAdd(&g_stat[it],
                          (1ULL << CNT_SHIFT) +
                          (u64)((double)s * 4294967296.0));
                int dn = 0;
                if (it > 0) {
                    while ((vstat >> CNT_SHIFT) < NUNITS) {
                        asm volatile("ld.global.cg.u64 %0, [%1];"
                                     : "=l"(vstat) : "l"(g_stat + (it - 1)));
                    }
                    dn = (vstat & ERR_MASK) < ERR_THRESH;
                }
                *flagI = dn;
            }
        }
        __syncthreads();
        if (*flagI) { fin = true; break; }
    }

    const float* xf = fin ? xog : xb;
    out[(r0 + (tid & 7)) * 64 + (tid >> 3)] = xf[tid] + zb[tid];
}

extern "C" void kernel_launch(void* const* d_in, const int* in_sizes, int n_in,
                              void* d_out, int out_size) {
    const float* x   = (const float*)d_in[0];
    const float* Wy0 = (const float*)d_in[1];
    const float* by0 = (const float*)d_in[2];
    const float* Wy1 = (const float*)d_in[3];
    const float* by1 = (const float*)d_in[4];
    const float* Wz1 = (const float*)d_in[5];
    const float* Wy2 = (const float*)d_in[6];
    const float* by2 = (const float*)d_in[7];
    const float* Wz2 = (const float*)d_in[8];
    float* out = (float*)d_out;

    static bool attr_set = false;
    if (!attr_set) {
        cudaFuncSetAttribute(blnn_main_kernel,
                             cudaFuncAttributeMaxDynamicSharedMemorySize,
                             SMEM_BYTES);
        attr_set = true;
    }

    blnn_init_kernel<<<1, 512>>>();
    blnn_main_kernel<<<NCTA, THREADS, SMEM_BYTES>>>(x, Wy0, by0, Wy1, by1, Wz1,
                                                    Wy2, by2, Wz2, out);
}

// round 6
// speedup vs baseline: 1.9757x; 1.0003x over previous
#include <cuda_runtime.h>
#include <cstdint>

// ---------------------------------------------------------------------------
// BLNN round 5: f32x2-packed FMA + distributed combines, no spills.
//  16 warps/CTA cooperate on 8 rows; accumulators are f32x2 (u64) pairs.
//  Stages A/B/C quarter-split over contraction dim, D oct-split; ALL quarters
//  store partials, then all 512 threads combine 2 of 1024 (h,row) outputs
//  each (consecutive-float loads, activations spread over all warps).
//  sg0 / sg2 persist in the consuming thread's registers across stages.
//  Weights single-copy, conflict-free both directions (stride-129 pads).
//  Convergence protocol unchanged from R4 (u64 atomic {cnt<<52|err}).
// ---------------------------------------------------------------------------

#define NCTA      128
#define THREADS   512
#define NUNITS    128ULL
#define MAX_IT    500
#define CNT_SHIFT 52
#define ERR_MASK  ((1ULL << 52) - 1)
#define ERR_THRESH 4398046511ULL   // 0.001*1024*2^32

typedef unsigned long long u64;

__device__ u64 g_stat[MAX_IT];

__global__ void blnn_init_kernel() {
    int i = blockIdx.x * blockDim.x + threadIdx.x;
    if (i < MAX_IT) g_stat[i] = 0ULL;
}

__device__ __forceinline__ u64 dup2(float w) {
    u64 r; asm("mov.b64 %0,{%1,%1};" : "=l"(r) : "f"(w)); return r;
}
__device__ __forceinline__ u64 fma2(u64 a, u64 b, u64 c) {
    u64 d; asm("fma.rn.f32x2 %0,%1,%2,%3;" : "=l"(d) : "l"(a), "l"(b), "l"(c));
    return d;
}
// softplus + sigmoid sharing one exp
__device__ __forceinline__ void act2(float a, float& sp, float& sg) {
    float e = __expf(-fabsf(a));
    float u = 1.0f + e;
    float r = __fdividef(1.0f, u);
    sp = fmaxf(a, 0.0f) + __logf(u);
    sg = (a >= 0.0f) ? r : e * r;
}

// ---- shared layout (float offsets) ----
#define OFF_WZ1T  0        // 16512
#define OFF_WY0T  16512    // 8256
#define OFF_WY1T  24768    // 8256
#define OFF_WY2V  33024    // 64
#define OFF_WZ2V  33088    // 128
#define OFF_BY0V  33216    // 128
#define OFF_BY1V  33344    // 128
#define OFF_XB    33472    // 512  [c*8+r]
#define OFF_XOLD  33984    // 512
#define OFF_ZB    34496    // 512
#define OFF_H0B   35008    // 1024 [h*8+r]
#define OFF_D1B   36032    // 1024
#define OFF_D0B   37056    // 1024
#define OFF_RED   38080    // 4096
#define OFF_S2P   42176    // 128 (16 warps x 8)
#define OFF_NRMP  42304    // 128
#define OFF_WYP   42432    // 128
#define OFF_WY2X  42560    // 8
#define OFF_MISC  42568    // 8  [0]=by2, int[1]=flag
#define SMEM_FLOATS 42576
#define SMEM_BYTES  (SMEM_FLOATS * 4)

__global__ void __launch_bounds__(THREADS, 1)
blnn_main_kernel(const float* __restrict__ x_in,
                 const float* __restrict__ Wy0, const float* __restrict__ by0,
                 const float* __restrict__ Wy1, const float* __restrict__ by1,
                 const float* __restrict__ Wz1,
                 const float* __restrict__ Wy2, const float* __restrict__ by2,
                 const float* __restrict__ Wz2,
                 float* __restrict__ out)
{
    extern __shared__ float sm[];
    float* wz1t = sm + OFF_WZ1T;
    float* wy0t = sm + OFF_WY0T;
    float* wy1t = sm + OFF_WY1T;
    float* wy2v = sm + OFF_WY2V;
    float* wz2v = sm + OFF_WZ2V;
    float* by0v = sm + OFF_BY0V;
    float* by1v = sm + OFF_BY1V;
    float* xb   = sm + OFF_XB;
    float* xog  = sm + OFF_XOLD;
    float* zb   = sm + OFF_ZB;
    float* h0b  = sm + OFF_H0B;
    float* d1b  = sm + OFF_D1B;
    float* d0b  = sm + OFF_D0B;
    float* red  = sm + OFF_RED;
    float* s2p  = sm + OFF_S2P;
    float* nrmp = sm + OFF_NRMP;
    float* wyp  = sm + OFF_WYP;
    float* wy2x = sm + OFF_WY2X;
    float* misc = sm + OFF_MISC;
    volatile int* flagI = (volatile int*)(misc + 1);

    const int tid  = threadIdx.x;
    const int l    = tid & 31;
    const int warp = tid >> 5;
    const int qc   = tid >> 7;       // stage A/B/C contraction quarter
    const int hh   = tid & 127;      // owned h in partial loops
    const int oc   = tid >> 6;       // stage D h-oct
    const int c    = tid & 63;       // owned c in stage D partial

    // ---- one-time staging ----
    for (int idx = tid; idx < 128 * 128; idx += THREADS) {
        int j = idx >> 7, k = idx & 127;
        wz1t[k * 129 + j] = fmaxf(Wz1[idx], 0.0f);
    }
    for (int idx = tid; idx < 64 * 128; idx += THREADS) {
        int cc = idx >> 7, h = idx & 127;
        wy0t[cc * 129 + h] = Wy0[h * 64 + cc];
        wy1t[cc * 129 + h] = Wy1[h * 64 + cc];
    }
    if (tid < 64)  wy2v[tid] = Wy2[tid];
    if (tid < 128) {
        wz2v[tid] = fmaxf(Wz2[tid], 0.0f);
        by0v[tid] = by0[tid];
        by1v[tid] = by1[tid];
    }
    const int r0 = blockIdx.x * 8;
    zb[tid] = x_in[(r0 + (tid & 7)) * 64 + (tid >> 3)];
    xb[tid] = 1.0f;
    if (tid == 0) { misc[0] = by2[0]; *flagI = 0; }
    __syncthreads();
    if (tid == 0) {
        float s = 0.0f;
        for (int i = 0; i < 64; i++) s += wy2v[i];
        #pragma unroll
        for (int r = 0; r < 8; r++) wy2x[r] = s;   // x = 1 initially
    }
    __syncthreads();

    const float by2v = misc[0];
    bool fin = false;

    #pragma unroll 1
    for (int it = 0; it < MAX_IT; ++it) {
        u64 vstat = 0ULL;
        if (tid == 0 && it > 0) {
            asm volatile("ld.global.cg.u64 %0, [%1];"
                         : "=l"(vstat) : "l"(g_stat + (it - 1)));
        }

        // ============ stage A partial: Wy0 x (A) and Wy1 x (S) =============
        u64 A0 = 0, A1 = 0, A2_ = 0, A3 = 0;
        u64 S0 = 0, S1 = 0, S2_ = 0, S3 = 0;
        {
            const float* pw0 = wy0t + qc * 16 * 129 + hh;
            const float* pw1 = wy1t + qc * 16 * 129 + hh;
            const ulonglong2* px = (const ulonglong2*)(xb + qc * 16 * 8);
            #pragma unroll 2
            for (int cc = 0; cc < 16; cc++) {
                u64 w0 = dup2(pw0[cc * 129]);
                u64 w1 = dup2(pw1[cc * 129]);
                ulonglong2 xlo = px[cc * 2];
                ulonglong2 xhi = px[cc * 2 + 1];
                A0 = fma2(w0, xlo.x, A0);  A1 = fma2(w0, xlo.y, A1);
                A2_ = fma2(w0, xhi.x, A2_); A3 = fma2(w0, xhi.y, A3);
                S0 = fma2(w1, xlo.x, S0);  S1 = fma2(w1, xlo.y, S1);
                S2_ = fma2(w1, xhi.x, S2_); S3 = fma2(w1, xhi.y, S3);
            }
        }
        {
            ulonglong2* pr = (ulonglong2*)(red + qc * 1024 + hh * 8);
            pr[0] = make_ulonglong2(A0, A1);
            pr[1] = make_ulonglong2(A2_, A3);
        }
        __syncthreads();

        // ---- A combine: each thread owns v=tid and v=tid+512 --------------
        float sg0a, sg0b_;
        {
            float a0 = red[tid] + red[1024 + tid] + red[2048 + tid] +
                       red[3072 + tid] + by0v[tid >> 3];
            float a1 = red[512 + tid] + red[1536 + tid] + red[2560 + tid] +
                       red[3584 + tid] + by0v[64 + (tid >> 3)];
            float h0a, h0bv;
            act2(a0, h0a, sg0a);
            act2(a1, h0bv, sg0b_);
            h0b[tid] = h0a;
            h0b[512 + tid] = h0bv;
        }
        __syncthreads();

        // ============ stage B partial: S += Wz1c h0 ========================
        {
            const float* pw = wz1t + qc * 32 * 129 + hh;
            const ulonglong2* ph = (const ulonglong2*)(h0b + qc * 32 * 8);
            #pragma unroll 4
            for (int kk = 0; kk < 32; kk++) {
                u64 w = dup2(pw[kk * 129]);
                ulonglong2 hlo = ph[kk * 2];
                ulonglong2 hhi = ph[kk * 2 + 1];
                S0 = fma2(w, hlo.x, S0);  S1 = fma2(w, hlo.y, S1);
                S2_ = fma2(w, hhi.x, S2_); S3 = fma2(w, hhi.y, S3);
            }
        }
        {
            ulonglong2* pr = (ulonglong2*)(red + qc * 1024 + hh * 8);
            pr[0] = make_ulonglong2(S0, S1);
            pr[1] = make_ulonglong2(S2_, S3);
        }
        __syncthreads();

        // ---- B combine: h1/sg1, s2 partial reduce --------------------------
        float sg2, d1a, d1bv;
        float wz2a, wz2b, sg1a, sg1b;
        {
            float s1a = red[tid] + red[1024 + tid] + red[2048 + tid] +
                        red[3072 + tid] + by1v[tid >> 3];
            float s1b = red[512 + tid] + red[1536 + tid] + red[2560 + tid] +
                        red[3584 + tid] + by1v[64 + (tid >> 3)];
            float h1a, h1b;
            act2(s1a, h1a, sg1a);
            act2(s1b, h1b, sg1b);
            wz2a = wz2v[tid >> 3];
            wz2b = wz2v[64 + (tid >> 3)];
            float s2c = wz2a * h1a + wz2b * h1b;
            s2c += __shfl_xor_sync(0xffffffffu, s2c, 8);
            s2c += __shfl_xor_sync(0xffffffffu, s2c, 16);
            if (l < 8) s2p[warp * 8 + l] = s2c;
        }
        __syncthreads();
        {
            float s2tot = 0.0f;
            #pragma unroll
            for (int w = 0; w < 16; w++) s2tot += s2p[w * 8 + (tid & 7)];
            float e = __expf(-(s2tot + wy2x[tid & 7] + by2v));
            sg2 = __fdividef(1.0f, 1.0f + e);
            d1a  = wz2a * sg1a * sg2;
            d1bv = wz2b * sg1b * sg2;
            d1b[tid] = d1a;
            d1b[512 + tid] = d1bv;
        }
        __syncthreads();

        // ============ stage C partial: Wz1c^T d1 ===========================
        {
            u64 C0 = 0, C1 = 0, C2_ = 0, C3 = 0;
            const float* pw = wz1t + hh * 129 + qc * 32;
            const ulonglong2* pd = (const ulonglong2*)(d1b + qc * 32 * 8);
            #pragma unroll 4
            for (int jj = 0; jj < 32; jj++) {
                u64 w = dup2(pw[jj]);
                ulonglong2 dlo = pd[jj * 2];
                ulonglong2 dhi = pd[jj * 2 + 1];
                C0 = fma2(w, dlo.x, C0);  C1 = fma2(w, dlo.y, C1);
                C2_ = fma2(w, dhi.x, C2_); C3 = fma2(w, dhi.y, C3);
            }
            ulonglong2* pr = (ulonglong2*)(red + qc * 1024 + hh * 8);
            pr[0] = make_ulonglong2(C0, C1);
            pr[1] = make_ulonglong2(C2_, C3);
        }
        __syncthreads();
        // ---- C combine: d0 = sg0 * sum ------------------------------------
        {
            float c0s = red[tid] + red[1024 + tid] + red[2048 + tid] +
                        red[3072 + tid];
            float c1s = red[512 + tid] + red[1536 + tid] + red[2560 + tid] +
                        red[3584 + tid];
            d0b[tid] = sg0a * c0s;
            d0b[512 + tid] = sg0b_ * c1s;
        }
        __syncthreads();

        // ============ stage D partial: Wy1^T d1 + Wy0^T d0 =================
        {
            u64 G0 = 0, G1 = 0, G2_ = 0, G3 = 0;
            const float* pw1 = wy1t + c * 129 + oc * 16;
            const float* pw0 = wy0t + c * 129 + oc * 16;
            const ulonglong2* pd1 = (const ulonglong2*)(d1b + oc * 16 * 8);
            const ulonglong2* pd0 = (const ulonglong2*)(d0b + oc * 16 * 8);
            #pragma unroll 2
            for (int h2 = 0; h2 < 16; h2++) {
                u64 w1 = dup2(pw1[h2]);
                u64 w0 = dup2(pw0[h2]);
                ulonglong2 alo = pd1[h2 * 2];
                ulonglong2 ahi = pd1[h2 * 2 + 1];
                ulonglong2 blo = pd0[h2 * 2];
                ulonglong2 bhi = pd0[h2 * 2 + 1];
                G0 = fma2(w1, alo.x, G0);  G1 = fma2(w1, alo.y, G1);
                G2_ = fma2(w1, ahi.x, G2_); G3 = fma2(w1, ahi.y, G3);
                G0 = fma2(w0, blo.x, G0);  G1 = fma2(w0, blo.y, G1);
                G2_ = fma2(w0, bhi.x, G2_); G3 = fma2(w0, bhi.y, G3);
            }
            ulonglong2* pr = (ulonglong2*)(red + oc * 512 + c * 8);
            pr[0] = make_ulonglong2(G0, G1);
            pr[1] = make_ulonglong2(G2_, G3);
        }
        __syncthreads();

        // ---- D combine: residual, update, norm partials --------------------
        {
            float gs = red[tid] + red[512 + tid] + red[1024 + tid] +
                       red[1536 + tid] + red[2048 + tid] + red[2560 + tid] +
                       red[3072 + tid] + red[3584 + tid];
            float xc = xb[tid];
            float zz = zb[tid];
            float wy2c = wy2v[tid >> 3];
            float gf = gs + xc + sg2 * wy2c;
            float rv = zz - gf;
            float nn = rv * rv;
            float lr = 2.0f / ((float)it + 1.0f);
            float xn = fmaf(lr, rv, xc);
            xog[tid] = xc;
            xb[tid] = xn;
            float p2 = wy2c * xn;
            nn += __shfl_xor_sync(0xffffffffu, nn, 8);
            nn += __shfl_xor_sync(0xffffffffu, nn, 16);
            p2 += __shfl_xor_sync(0xffffffffu, p2, 8);
            p2 += __shfl_xor_sync(0xffffffffu, p2, 16);
            if (l < 8) { nrmp[warp * 8 + l] = nn; wyp[warp * 8 + l] = p2; }
        }
        __syncthreads();

        // ============ convergence ==========================================
        if (tid < 8) {
            float nr = 0.0f, ws = 0.0f;
            #pragma unroll
            for (int w = 0; w < 16; w++) {
                nr += nrmp[w * 8 + tid];
                ws += wyp[w * 8 + tid];
            }
            wy2x[tid] = ws;
            float s = sqrtf(nr);
            s += __shfl_xor_sync(0xffu, s, 4, 8);
            s += __shfl_xor_sync(0xffu, s, 2, 8);
            s += __shfl_xor_sync(0xffu, s, 1, 8);
            if (tid == 0) {
                atomicAdd(&g_stat[it],
                          (1ULL << CNT_SHIFT) +
                          (u64)((double)s * 4294967296.0));
                int dn = 0;
                if (it > 0) {
                    while ((vstat >> CNT_SHIFT) < NUNITS) {
                        asm volatile("ld.global.cg.u64 %0, [%1];"
                                     : "=l"(vstat) : "l"(g_stat + (it - 1)));
                    }
                    dn = (vstat & ERR_MASK) < ERR_THRESH;
                }
                *flagI = dn;
            }
        }
        __syncthreads();
        if (*flagI) { fin = true; break; }
    }

    const float* xf = fin ? xog : xb;
    out[(r0 + (tid & 7)) * 64 + (tid >> 3)] = xf[tid] + zb[tid];
}

extern "C" void kernel_launch(void* const* d_in, const int* in_sizes, int n_in,
                              void* d_out, int out_size) {
    const float* x   = (const float*)d_in[0];
    const float* Wy0 = (const float*)d_in[1];
    const float* by0 = (const float*)d_in[2];
    const float* Wy1 = (const float*)d_in[3];
    const float* by1 = (const float*)d_in[4];
    const float* Wz1 = (const float*)d_in[5];
    const float* Wy2 = (const float*)d_in[6];
    const float* by2 = (const float*)d_in[7];
    const float* Wz2 = (const float*)d_in[8];
    float* out = (float*)d_out;

    static bool attr_set = false;
    if (!attr_set) {
        cudaFuncSetAttribute(blnn_main_kernel,
                             cudaFuncAttributeMaxDynamicSharedMemorySize,
                             SMEM_BYTES);
        attr_set = true;
    }

    blnn_init_kernel<<<1, 512>>>();
    blnn_main_kernel<<<NCTA, THREADS, SMEM_BYTES>>>(x, Wy0, by0, Wy1, by1, Wz1,
                                                    Wy2, by2, Wz2, out);
}

// round 7
// speedup vs baseline: 2.2127x; 1.1200x over previous
#include <cuda_runtime.h>
#include <cstdint>

// ---------------------------------------------------------------------------
// BLNN round 7: 2 outputs/lane GEMVs, Lo/Hi split buffers, deferred sg2.
// ---------------------------------------------------------------------------

#define NCTA      128
#define THREADS   512
#define NUNITS    128ULL
#define MAX_IT    500
#define CNT_SHIFT 52
#define ERR_MASK  ((1ULL << 52) - 1)
#define ERR_THRESH 4398046511ULL   // 0.001*1024*2^32

typedef unsigned long long u64;

__device__ u64 g_stat[MAX_IT];

__global__ void blnn_init_kernel() {
    int i = blockIdx.x * blockDim.x + threadIdx.x;
    if (i < MAX_IT) g_stat[i] = 0ULL;
}

__device__ __forceinline__ u64 dup2(float w) {
    u64 r; asm("mov.b64 %0,{%1,%1};" : "=l"(r) : "f"(w)); return r;
}
__device__ __forceinline__ u64 fma2(u64 a, u64 b, u64 c) {
    u64 d; asm("fma.rn.f32x2 %0,%1,%2,%3;" : "=l"(d) : "l"(a), "l"(b), "l"(c));
    return d;
}
__device__ __forceinline__ void act2(float a, float& sp, float& sg) {
    float e = __expf(-fabsf(a));
    float u = 1.0f + e;
    float r = __fdividef(1.0f, u);
    sp = fmaxf(a, 0.0f) + __logf(u);
    sg = (a >= 0.0f) ? r : e * r;
}

// ---- shared layout (float offsets; all float4-aligned) ----
#define OFF_WZ1T  0
#define OFF_WY0T  16512
#define OFF_WY1T  24768
#define OFF_WY2V  33024
#define OFF_WZ2V  33088
#define OFF_BY0V  33216
#define OFF_BY1V  33344
#define OFF_XLO   33472
#define OFF_XHI   33728
#define OFF_XOLO  33984
#define OFF_XOHI  34240
#define OFF_ZLO   34496
#define OFF_ZHI   34752
#define OFF_H0LO  35008
#define OFF_H0HI  35520
#define OFF_D1LO  36032
#define OFF_D1HI  36544
#define OFF_D0LO  37056
#define OFF_D0HI  37568
#define OFF_RLO   38080   // 4096
#define OFF_RHI   42176   // 4096
#define OFF_S2PL  46272   // 64
#define OFF_S2PH  46336   // 64
#define OFF_SG2S  46400   // 8
#define OFF_NRMP  46408   // 64
#define OFF_WYP   46472   // 64
#define OFF_WY2X  46536   // 8
#define OFF_MISC  46544   // 8
#define SMEM_FLOATS 46552
#define SMEM_BYTES  (SMEM_FLOATS * 4)

__global__ void __launch_bounds__(THREADS, 1)
blnn_main_kernel(const float* __restrict__ x_in,
                 const float* __restrict__ Wy0, const float* __restrict__ by0,
                 const float* __restrict__ Wy1, const float* __restrict__ by1,
                 const float* __restrict__ Wz1,
                 const float* __restrict__ Wy2, const float* __restrict__ by2,
                 const float* __restrict__ Wz2,
                 float* __restrict__ out)
{
    extern __shared__ float sm[];
    float* wz1t = sm + OFF_WZ1T;
    float* wy0t = sm + OFF_WY0T;
    float* wy1t = sm + OFF_WY1T;
    float* wy2v = sm + OFF_WY2V;
    float* wz2v = sm + OFF_WZ2V;
    float* by0v = sm + OFF_BY0V;
    float* by1v = sm + OFF_BY1V;
    float* xLo  = sm + OFF_XLO;   float* xHi  = sm + OFF_XHI;
    float* xoLo = sm + OFF_XOLO;  float* xoHi = sm + OFF_XOHI;
    float* zLo  = sm + OFF_ZLO;   float* zHi  = sm + OFF_ZHI;
    float* h0Lo = sm + OFF_H0LO;  float* h0Hi = sm + OFF_H0HI;
    float* d1Lo = sm + OFF_D1LO;  float* d1Hi = sm + OFF_D1HI;
    float* d0Lo = sm + OFF_D0LO;  float* d0Hi = sm + OFF_D0HI;
    float* rLo  = sm + OFF_RLO;   float* rHi  = sm + OFF_RHI;
    float* s2pL = sm + OFF_S2PL;  float* s2pH = sm + OFF_S2PH;
    float* sg2s = sm + OFF_SG2S;
    float* nrmp = sm + OFF_NRMP;  float* wyp  = sm + OFF_WYP;
    float* wy2x = sm + OFF_WY2X;  float* misc = sm + OFF_MISC;
    volatile int* flagI = (volatile int*)(misc + 1);

    const int tid  = threadIdx.x;
    const int l    = tid & 31;
    const int warp = tid >> 5;
    const int g    = warp & 1;        // h-group (GEMV A/B/C)
    const int ch   = warp >> 1;       // contraction chunk 0..7
    const int hA   = g * 64 + l;      // owned outputs (A/B/C)
    const int hB   = hA + 32;
    const int cA   = l, cB = l + 32;  // owned outputs (D)
    // combine mapping (A/B/C): thread -> (hC, rl) in both halves
    const int hC = tid >> 2, rl = tid & 3;
    // combine mapping (D): 512 outputs, one per thread
    const int half = tid >> 8, idxD = tid & 255;
    const int cD = idxD >> 2, rlD = idxD & 3;

    // ---- one-time staging ----
    for (int idx = tid; idx < 128 * 128; idx += THREADS) {
        int j = idx >> 7, k = idx & 127;
        wz1t[k * 129 + j] = fmaxf(Wz1[idx], 0.0f);
    }
    for (int idx = tid; idx < 64 * 128; idx += THREADS) {
        int cc = idx >> 7, h = idx & 127;
        wy0t[cc * 129 + h] = Wy0[h * 64 + cc];
        wy1t[cc * 129 + h] = Wy1[h * 64 + cc];
    }
    if (tid < 64)  wy2v[tid] = Wy2[tid];
    if (tid < 128) {
        wz2v[tid] = fmaxf(Wz2[tid], 0.0f);
        by0v[tid] = by0[tid];
        by1v[tid] = by1[tid];
    }
    const int r0 = blockIdx.x * 8;
    if (tid < 256) { zLo[tid] = x_in[(r0 + rl) * 64 + hC]; xLo[tid] = 1.0f; }
    else { zHi[idxD] = x_in[(r0 + 4 + rlD) * 64 + cD * 4 / 4 + (idxD >> 2) - cD + cD] , xHi[idxD] = 1.0f; }
    // (fix the zHi expression cleanly below)
    if (tid >= 256) zHi[idxD] = x_in[(r0 + 4 + rlD) * 64 + (idxD >> 2)];
    if (tid == 0) { misc[0] = by2[0]; *flagI = 0; }
    __syncthreads();
    if (tid == 0) {
        float s = 0.0f;
        for (int i = 0; i < 64; i++) s += wy2v[i];
        #pragma unroll
        for (int r = 0; r < 8; r++) wy2x[r] = s;   // x = 1 initially
    }
    __syncthreads();

    const float by2v = misc[0];
    bool fin = false;

    #pragma unroll 1
    for (int it = 0; it < MAX_IT; ++it) {
        u64 vstat = 0ULL;
        if (tid == 0 && it > 0) {
            asm volatile("ld.global.cg.u64 %0, [%1];"
                         : "=l"(vstat) : "l"(g_stat + (it - 1)));
        }

        // ===== stage A: A = Wy0 x ; S = Wy1 x  (8-c chunks, 2 h/lane) ======
        u64 A0=0,A1=0,A2=0,A3=0,A4=0,A5=0,A6=0,A7=0;
        u64 S0=0,S1=0,S2=0,S3=0,S4=0,S5=0,S6=0,S7=0;
        {
            const float* p0 = wy0t + ch * 8 * 129;
            const float* p1 = wy1t + ch * 8 * 129;
            const float* pxl = xLo + ch * 8 * 4;
            const float* pxh = xHi + ch * 8 * 4;
            #pragma unroll 2
            for (int cc = 0; cc < 8; cc++) {
                u64 w0A = dup2(p0[cc * 129 + hA]);
                u64 w0B = dup2(p0[cc * 129 + hB]);
                u64 w1A = dup2(p1[cc * 129 + hA]);
                u64 w1B = dup2(p1[cc * 129 + hB]);
                ulonglong2 xl = *(const ulonglong2*)(pxl + cc * 4);
                ulonglong2 xh = *(const ulonglong2*)(pxh + cc * 4);
                A0=fma2(w0A,xl.x,A0); A1=fma2(w0A,xl.y,A1);
                A2=fma2(w0A,xh.x,A2); A3=fma2(w0A,xh.y,A3);
                A4=fma2(w0B,xl.x,A4); A5=fma2(w0B,xl.y,A5);
                A6=fma2(w0B,xh.x,A6); A7=fma2(w0B,xh.y,A7);
                S0=fma2(w1A,xl.x,S0); S1=fma2(w1A,xl.y,S1);
                S2=fma2(w1A,xh.x,S2); S3=fma2(w1A,xh.y,S3);
                S4=fma2(w1B,xl.x,S4); S5=fma2(w1B,xl.y,S5);
                S6=fma2(w1B,xh.x,S6); S7=fma2(w1B,xh.y,S7);
            }
        }
        *(ulonglong2*)(rLo + ch * 512 + hA * 4) = make_ulonglong2(A0, A1);
        *(ulonglong2*)(rHi + ch * 512 + hA * 4) = make_ulonglong2(A2, A3);
        *(ulonglong2*)(rLo + ch * 512 + hB * 4) = make_ulonglong2(A4, A5);
        *(ulonglong2*)(rHi + ch * 512 + hB * 4) = make_ulonglong2(A6, A7);
        __syncthreads();

        // ---- combine A: h0 = softplus, keep sg0 in regs -------------------
        float sg0L, sg0H;
        {
            float aL = by0v[hC], aH = aL;
            #pragma unroll
            for (int p = 0; p < 8; p++) {
                aL += rLo[p * 512 + tid];
                aH += rHi[p * 512 + tid];
            }
            float hL, hH;
            act2(aL, hL, sg0L);
            act2(aH, hH, sg0H);
            h0Lo[tid] = hL;
            h0Hi[tid] = hH;
        }
        __syncthreads();

        // ===== stage B: S += Wz1c h0  (8-k chunks, 2 h/lane) ===============
        {
            const float* pz = wz1t + ch * 16 * 129;
            const float* phl = h0Lo + ch * 16 * 4;
            const float* phh = h0Hi + ch * 16 * 4;
            #pragma unroll 4
            for (int kk = 0; kk < 16; kk++) {
                u64 wA = dup2(pz[kk * 129 + hA]);
                u64 wB = dup2(pz[kk * 129 + hB]);
                ulonglong2 hl = *(const ulonglong2*)(phl + kk * 4);
                ulonglong2 hh2 = *(const ulonglong2*)(phh + kk * 4);
                S0=fma2(wA,hl.x,S0); S1=fma2(wA,hl.y,S1);
                S2=fma2(wA,hh2.x,S2); S3=fma2(wA,hh2.y,S3);
                S4=fma2(wB,hl.x,S4); S5=fma2(wB,hl.y,S5);
                S6=fma2(wB,hh2.x,S6); S7=fma2(wB,hh2.y,S7);
            }
        }
        *(ulonglong2*)(rLo + ch * 512 + hA * 4) = make_ulonglong2(S0, S1);
        *(ulonglong2*)(rHi + ch * 512 + hA * 4) = make_ulonglong2(S2, S3);
        *(ulonglong2*)(rLo + ch * 512 + hB * 4) = make_ulonglong2(S4, S5);
        *(ulonglong2*)(rHi + ch * 512 + hB * 4) = make_ulonglong2(S6, S7);
        __syncthreads();

        // ---- combine B: d1' = wz2*sg1 (sg2 deferred); s2 warp partials ----
        {
            float sL = by1v[hC], sH = sL;
            #pragma unroll
            for (int p = 0; p < 8; p++) {
                sL += rLo[p * 512 + tid];
                sH += rHi[p * 512 + tid];
            }
            float h1L, h1H, sg1L, sg1H;
            act2(sL, h1L, sg1L);
            act2(sH, h1H, sg1H);
            float wz2h = wz2v[hC];
            d1Lo[tid] = wz2h * sg1L;
            d1Hi[tid] = wz2h * sg1H;
            float s2L = wz2h * h1L, s2H = wz2h * h1H;
            #pragma unroll
            for (int o = 4; o < 32; o <<= 1) {
                s2L += __shfl_xor_sync(0xffffffffu, s2L, o);
                s2H += __shfl_xor_sync(0xffffffffu, s2H, o);
            }
            if (l < 4) { s2pL[warp * 4 + l] = s2L; s2pH[warp * 4 + l] = s2H; }
        }
        __syncthreads();

        // ---- sg2 finalize (8 threads, overlaps stage C) -------------------
        if (tid < 8) {
            const float* sp = (tid & 4) ? s2pH : s2pL;
            int rr = tid & 3;
            float s2t = 0.0f;
            #pragma unroll
            for (int w = 0; w < 16; w++) s2t += sp[w * 4 + rr];
            float e = __expf(-(s2t + wy2x[tid] + by2v));
            sg2s[tid] = __fdividef(1.0f, 1.0f + e);
        }

        // ===== stage C: Wz1c^T d1' (8-j chunks, 2 k/lane) ==================
        {
            u64 C0=0,C1=0,C2=0,C3=0,C4=0,C5=0,C6=0,C7=0;
            const float* pzA = wz1t + hA * 129 + ch * 16;
            const float* pzB = wz1t + hB * 129 + ch * 16;
            const float* pdl = d1Lo + ch * 16 * 4;
            const float* pdh = d1Hi + ch * 16 * 4;
            #pragma unroll 4
            for (int jj = 0; jj < 16; jj++) {
                u64 wA = dup2(pzA[jj]);
                u64 wB = dup2(pzB[jj]);
                ulonglong2 dl = *(const ulonglong2*)(pdl + jj * 4);
                ulonglong2 dh = *(const ulonglong2*)(pdh + jj * 4);
                C0=fma2(wA,dl.x,C0); C1=fma2(wA,dl.y,C1);
                C2=fma2(wA,dh.x,C2); C3=fma2(wA,dh.y,C3);
                C4=fma2(wB,dl.x,C4); C5=fma2(wB,dl.y,C5);
                C6=fma2(wB,dh.x,C6); C7=fma2(wB,dh.y,C7);
            }
            *(ulonglong2*)(rLo + ch * 512 + hA * 4) = make_ulonglong2(C0, C1);
            *(ulonglong2*)(rHi + ch * 512 + hA * 4) = make_ulonglong2(C2, C3);
            *(ulonglong2*)(rLo + ch * 512 + hB * 4) = make_ulonglong2(C4, C5);
            *(ulonglong2*)(rHi + ch * 512 + hB * 4) = make_ulonglong2(C6, C7);
        }
        __syncthreads();

        // ---- combine C: d0' = sg0 * sum -----------------------------------
        {
            float cL = 0.0f, cH = 0.0f;
            #pragma unroll
            for (int p = 0; p < 8; p++) {
                cL += rLo[p * 512 + tid];
                cH += rHi[p * 512 + tid];
            }
            d0Lo[tid] = sg0L * cL;
            d0Hi[tid] = sg0H * cH;
        }
        __syncthreads();

        // ===== stage D: Wy1^T d1' + Wy0^T d0' (16 h-chunks, 2 c/lane) ======
        {
            u64 G0=0,G1=0,G2=0,G3=0,G4=0,G5=0,G6=0,G7=0;
            const float* p1A = wy1t + cA * 129 + warp * 8;
            const float* p1B = wy1t + cB * 129 + warp * 8;
            const float* p0A = wy0t + cA * 129 + warp * 8;
            const float* p0B = wy0t + cB * 129 + warp * 8;
            const float* q1l = d1Lo + warp * 8 * 4;
            const float* q1h = d1Hi + warp * 8 * 4;
            const float* q0l = d0Lo + warp * 8 * 4;
            const float* q0h = d0Hi + warp * 8 * 4;
            #pragma unroll 2
            for (int h2 = 0; h2 < 8; h2++) {
                u64 w1A = dup2(p1A[h2]);
                u64 w1B = dup2(p1B[h2]);
                u64 w0A = dup2(p0A[h2]);
                u64 w0B = dup2(p0B[h2]);
                ulonglong2 al = *(const ulonglong2*)(q1l + h2 * 4);
                ulonglong2 ah = *(const ulonglong2*)(q1h + h2 * 4);
                ulonglong2 bl = *(const ulonglong2*)(q0l + h2 * 4);
                ulonglong2 bh = *(const ulonglong2*)(q0h + h2 * 4);
                G0=fma2(w1A,al.x,G0); G1=fma2(w1A,al.y,G1);
                G2=fma2(w1A,ah.x,G2); G3=fma2(w1A,ah.y,G3);
                G0=fma2(w0A,bl.x,G0); G1=fma2(w0A,bl.y,G1);
                G2=fma2(w0A,bh.x,G2); G3=fma2(w0A,bh.y,G3);
                G4=fma2(w1B,al.x,G4); G5=fma2(w1B,al.y,G5);
                G6=fma2(w1B,ah.x,G6); G7=fma2(w1B,ah.y,G7);
                G4=fma2(w0B,bl.x,G4); G5=fma2(w0B,bl.y,G5);
                G6=fma2(w0B,bh.x,G6); G7=fma2(w0B,bh.y,G7);
            }
            *(ulonglong2*)(rLo + warp * 256 + cA * 4) = make_ulonglong2(G0, G1);
            *(ulonglong2*)(rHi + warp * 256 + cA * 4) = make_ulonglong2(G2, G3);
            *(ulonglong2*)(rLo + warp * 256 + cB * 4) = make_ulonglong2(G4, G5);
            *(ulonglong2*)(rHi + warp * 256 + cB * 4) = make_ulonglong2(G6, G7);
        }
        __syncthreads();

        // ---- combine D: residual, update, norm/wy2x partials --------------
        {
            const float* rX  = half ? rHi : rLo;
            float* xX  = half ? xHi : xLo;
            float* xoX = half ? xoHi : xoLo;
            const float* zX = half ? zHi : zLo;
            float gs = 0.0f;
            #pragma unroll
            for (int p = 0; p < 16; p++) gs += rX[p * 256 + idxD];
            float sg2 = sg2s[half * 4 + rlD];
            float wy2c = wy2v[cD];
            float xc = xX[idxD];
            float gf = fmaf(sg2, gs + wy2c, xc);
            float rv = zX[idxD] - gf;
            float nn = rv * rv;
            float lr = 2.0f / ((float)it + 1.0f);
            float xn = fmaf(lr, rv, xc);
            xoX[idxD] = xc;
            xX[idxD] = xn;
            float p2 = wy2c * xn;
            #pragma unroll
            for (int o = 4; o < 32; o <<= 1) {
                nn += __shfl_xor_sync(0xffffffffu, nn, o);
                p2 += __shfl_xor_sync(0xffffffffu, p2, o);
            }
            if (l < 4) { nrmp[warp * 4 + l] = nn; wyp[warp * 4 + l] = p2; }
        }
        __syncthreads();

        // ---- convergence ---------------------------------------------------
        if (tid < 8) {
            int hb = (tid >> 2) * 8, rr = tid & 3;
            float nr = 0.0f, ws = 0.0f;
            #pragma unroll
            for (int w = 0; w < 8; w++) {
                nr += nrmp[(hb + w) * 4 + rr];
                ws += wyp[(hb + w) * 4 + rr];
            }
            wy2x[tid] = ws;
            float s = sqrtf(nr);
            s += __shfl_xor_sync(0xffu, s, 4, 8);
            s += __shfl_xor_sync(0xffu, s, 2, 8);
            s += __shfl_xor_sync(0xffu, s, 1, 8);
            if (tid == 0) {
                atomicAdd(&g_stat[it],
                          (1ULL << CNT_SHIFT) +
                          (u64)((double)s * 4294967296.0));
                int dn = 0;
                if (it > 0) {
                    while ((vstat >> CNT_SHIFT) < NUNITS) {
                        asm volatile("ld.global.cg.u64 %0, [%1];"
                                     : "=l"(vstat) : "l"(g_stat + (it - 1)));
                    }
                    dn = (vstat & ERR_MASK) < ERR_THRESH;
                }
                *flagI = dn;
            }
        }
        __syncthreads();
        if (*flagI) { fin = true; break; }
    }

    {
        const float* xX = fin ? (half ? xoHi : xoLo) : (half ? xHi : xLo);
        const float* zX = half ? zHi : zLo;
        out[(r0 + half * 4 + rlD) * 64 + cD] = xX[idxD] + zX[idxD];
    }
}

extern "C" void kernel_launch(void* const* d_in, const int* in_sizes, int n_in,
                              void* d_out, int out_size) {
    const float* x   = (const float*)d_in[0];
    const float* Wy0 = (const float*)d_in[1];
    const float* by0 = (const float*)d_in[2];
    const float* Wy1 = (const float*)d_in[3];
    const float* by1 = (const float*)d_in[4];
    const float* Wz1 = (const float*)d_in[5];
    const float* Wy2 = (const float*)d_in[6];
    const float* by2 = (const float*)d_in[7];
    const float* Wz2 = (const float*)d_in[8];
    float* out = (float*)d_out;

    static bool attr_set = false;
    if (!attr_set) {
        cudaFuncSetAttribute(blnn_main_kernel,
                             cudaFuncAttributeMaxDynamicSharedMemorySize,
                             SMEM_BYTES);
        attr_set = true;
    }

    blnn_init_kernel<<<1, 512>>>();
    blnn_main_kernel<<<NCTA, THREADS, SMEM_BYTES>>>(x, Wy0, by0, Wy1, by1, Wz1,
                                                    Wy2, by2, Wz2, out);
}

// round 8
// speedup vs baseline: 2.3909x; 1.0805x over previous
#include <cuda_runtime.h>
#include <cstdint>

// ---------------------------------------------------------------------------
// BLNN round 8: R7 structure + f32x2-packed combines + deeper GEMV batching.
// ---------------------------------------------------------------------------

#define NCTA      128
#define THREADS   512
#define NUNITS    128ULL
#define MAX_IT    500
#define CNT_SHIFT 52
#define ERR_MASK  ((1ULL << 52) - 1)
#define ERR_THRESH 4398046511ULL   // 0.001*1024*2^32

typedef unsigned long long u64;

__device__ u64 g_stat[MAX_IT];

__global__ void blnn_init_kernel() {
    int i = blockIdx.x * blockDim.x + threadIdx.x;
    if (i < MAX_IT) g_stat[i] = 0ULL;
}

__device__ __forceinline__ u64 dup2(float w) {
    u64 r; asm("mov.b64 %0,{%1,%1};" : "=l"(r) : "f"(w)); return r;
}
__device__ __forceinline__ u64 fma2(u64 a, u64 b, u64 c) {
    u64 d; asm("fma.rn.f32x2 %0,%1,%2,%3;" : "=l"(d) : "l"(a), "l"(b), "l"(c));
    return d;
}
__device__ __forceinline__ float2 add2(float2 a, float2 b) {
    return make_float2(a.x + b.x, a.y + b.y);
}
__device__ __forceinline__ void act2(float a, float& sp, float& sg) {
    float e = __expf(-fabsf(a));
    float u = 1.0f + e;
    float r = __fdividef(1.0f, u);
    sp = fmaxf(a, 0.0f) + __logf(u);
    sg = (a >= 0.0f) ? r : e * r;
}

// ---- shared layout (float offsets; all 16B-aligned) ----
#define OFF_WZ1T  0
#define OFF_WY0T  16512
#define OFF_WY1T  24768
#define OFF_WY2V  33024
#define OFF_WZ2V  33088
#define OFF_BY0V  33216
#define OFF_BY1V  33344
#define OFF_XLO   33472
#define OFF_XHI   33728
#define OFF_XOLO  33984
#define OFF_XOHI  34240
#define OFF_ZLO   34496
#define OFF_ZHI   34752
#define OFF_H0LO  35008
#define OFF_H0HI  35520
#define OFF_D1LO  36032
#define OFF_D1HI  36544
#define OFF_D0LO  37056
#define OFF_D0HI  37568
#define OFF_RLO   38080   // 4096
#define OFF_RHI   42176   // 4096
#define OFF_S2PL  46272   // 32
#define OFF_S2PH  46304   // 32
#define OFF_SG2S  46336   // 8
#define OFF_NRMP  46344   // 32
#define OFF_WYP   46376   // 32
#define OFF_WY2X  46408   // 8
#define OFF_MISC  46416   // 8
#define SMEM_FLOATS 46424
#define SMEM_BYTES  (SMEM_FLOATS * 4)

__global__ void __launch_bounds__(THREADS, 1)
blnn_main_kernel(const float* __restrict__ x_in,
                 const float* __restrict__ Wy0, const float* __restrict__ by0,
                 const float* __restrict__ Wy1, const float* __restrict__ by1,
                 const float* __restrict__ Wz1,
                 const float* __restrict__ Wy2, const float* __restrict__ by2,
                 const float* __restrict__ Wz2,
                 float* __restrict__ out)
{
    extern __shared__ float sm[];
    float* wz1t = sm + OFF_WZ1T;
    float* wy0t = sm + OFF_WY0T;
    float* wy1t = sm + OFF_WY1T;
    float* wy2v = sm + OFF_WY2V;
    float* wz2v = sm + OFF_WZ2V;
    float* by0v = sm + OFF_BY0V;
    float* by1v = sm + OFF_BY1V;
    float* xLo  = sm + OFF_XLO;   float* xHi  = sm + OFF_XHI;
    float* xoLo = sm + OFF_XOLO;  float* xoHi = sm + OFF_XOHI;
    float* zLo  = sm + OFF_ZLO;   float* zHi  = sm + OFF_ZHI;
    float* h0Lo = sm + OFF_H0LO;  float* h0Hi = sm + OFF_H0HI;
    float* d1Lo = sm + OFF_D1LO;  float* d1Hi = sm + OFF_D1HI;
    float* d0Lo = sm + OFF_D0LO;  float* d0Hi = sm + OFF_D0HI;
    float* rLo  = sm + OFF_RLO;   float* rHi  = sm + OFF_RHI;
    float* s2pL = sm + OFF_S2PL;  float* s2pH = sm + OFF_S2PH;
    float* sg2s = sm + OFF_SG2S;
    float* nrmp = sm + OFF_NRMP;  float* wyp  = sm + OFF_WYP;
    float* wy2x = sm + OFF_WY2X;  float* misc = sm + OFF_MISC;
    volatile int* flagI = (volatile int*)(misc + 1);

    const int tid  = threadIdx.x;
    const int l    = tid & 31;
    const int warp = tid >> 5;
    // GEMV A/B/C mapping
    const int g    = warp & 1;        // h-group
    const int ch   = warp >> 1;       // contraction chunk 0..7
    const int hA   = g * 64 + l;
    const int hB   = hA + 32;
    const int cA   = l, cB = l + 32;  // stage D owned c
    // combine A/B/C mapping: (half, h, rl-pair)
    const int half = tid >> 8;        // 0 Lo, 1 Hi
    const int idx  = tid & 255;       // = 2*h + pr
    const int hQ   = idx >> 1;
    const int prQ  = idx & 1;
    const int wl   = warp & 7;        // warp-in-half
    // combine D mapping (tid < 256): (halfD, c, pr)
    const int halfD = tid >> 7;
    const int idx2  = tid & 127;      // = 2*c + pr
    const int cQ    = idx2 >> 1;
    const int prD   = idx2 & 1;

    // ---- one-time staging ----
    for (int i2 = tid; i2 < 128 * 128; i2 += THREADS) {
        int j = i2 >> 7, k = i2 & 127;
        wz1t[k * 129 + j] = fmaxf(Wz1[i2], 0.0f);
    }
    for (int i2 = tid; i2 < 64 * 128; i2 += THREADS) {
        int cc = i2 >> 7, h = i2 & 127;
        wy0t[cc * 129 + h] = Wy0[h * 64 + cc];
        wy1t[cc * 129 + h] = Wy1[h * 64 + cc];
    }
    if (tid < 64)  wy2v[tid] = Wy2[tid];
    if (tid < 128) {
        wz2v[tid] = fmaxf(Wz2[tid], 0.0f);
        by0v[tid] = by0[tid];
        by1v[tid] = by1[tid];
    }
    const int r0 = blockIdx.x * 8;
    {   // x buffers [c*4 + rl], z likewise; rows 0-3 Lo, 4-7 Hi
        int cc = tid >> 3, rr = tid & 7;
        float zv = x_in[(r0 + rr) * 64 + cc];
        if (rr < 4) { zLo[cc * 4 + rr] = zv; xLo[cc * 4 + rr] = 1.0f; }
        else        { zHi[cc * 4 + rr - 4] = zv; xHi[cc * 4 + rr - 4] = 1.0f; }
    }
    if (tid == 0) { misc[0] = by2[0]; *flagI = 0; }
    __syncthreads();
    if (tid == 0) {
        float s = 0.0f;
        for (int i2 = 0; i2 < 64; i2++) s += wy2v[i2];
        #pragma unroll
        for (int r = 0; r < 8; r++) wy2x[r] = s;   // x = 1 initially
    }
    __syncthreads();

    const float by2v = misc[0];
    bool fin = false;

    #pragma unroll 1
    for (int it = 0; it < MAX_IT; ++it) {
        u64 vstat = 0ULL;
        if (tid == 0 && it > 0) {
            asm volatile("ld.global.cg.u64 %0, [%1];"
                         : "=l"(vstat) : "l"(g_stat + (it - 1)));
        }

        // ===== stage A: A = Wy0 x ; S = Wy1 x  (8-c chunks, 2 h/lane) ======
        u64 S0=0,S1=0,S2=0,S3=0,S4=0,S5=0,S6=0,S7=0;
        {
            u64 A0=0,A1=0,A2=0,A3=0,A4=0,A5=0,A6=0,A7=0;
            const float* p0 = wy0t + ch * 8 * 129;
            const float* p1 = wy1t + ch * 8 * 129;
            const float* pxl = xLo + ch * 8 * 4;
            const float* pxh = xHi + ch * 8 * 4;
            #pragma unroll
            for (int cc = 0; cc < 8; cc++) {
                u64 w0A = dup2(p0[cc * 129 + hA]);
                u64 w0B = dup2(p0[cc * 129 + hB]);
                u64 w1A = dup2(p1[cc * 129 + hA]);
                u64 w1B = dup2(p1[cc * 129 + hB]);
                ulonglong2 xl = *(const ulonglong2*)(pxl + cc * 4);
                ulonglong2 xh = *(const ulonglong2*)(pxh + cc * 4);
                A0=fma2(w0A,xl.x,A0); A1=fma2(w0A,xl.y,A1);
                A2=fma2(w0A,xh.x,A2); A3=fma2(w0A,xh.y,A3);
                A4=fma2(w0B,xl.x,A4); A5=fma2(w0B,xl.y,A5);
                A6=fma2(w0B,xh.x,A6); A7=fma2(w0B,xh.y,A7);
                S0=fma2(w1A,xl.x,S0); S1=fma2(w1A,xl.y,S1);
                S2=fma2(w1A,xh.x,S2); S3=fma2(w1A,xh.y,S3);
                S4=fma2(w1B,xl.x,S4); S5=fma2(w1B,xl.y,S5);
                S6=fma2(w1B,xh.x,S6); S7=fma2(w1B,xh.y,S7);
            }
            *(ulonglong2*)(rLo + ch * 512 + hA * 4) = make_ulonglong2(A0, A1);
            *(ulonglong2*)(rHi + ch * 512 + hA * 4) = make_ulonglong2(A2, A3);
            *(ulonglong2*)(rLo + ch * 512 + hB * 4) = make_ulonglong2(A4, A5);
            *(ulonglong2*)(rHi + ch * 512 + hB * 4) = make_ulonglong2(A6, A7);
        }
        __syncthreads();

        // ---- combine A (f32x2): h0 + sg0 (sg0 pair kept in regs) ----------
        float sg0_0, sg0_1;
        {
            const float2* rp = (const float2*)(half ? rHi : rLo);
            float2 a = rp[idx];
            #pragma unroll
            for (int p = 1; p < 8; p++) a = add2(a, rp[p * 256 + idx]);
            float bv = by0v[hQ];
            float h0x, h0y;
            act2(a.x + bv, h0x, sg0_0);
            act2(a.y + bv, h0y, sg0_1);
            ((float2*)(half ? h0Hi : h0Lo))[idx] = make_float2(h0x, h0y);
        }
        __syncthreads();

        // ===== stage B: S += Wz1c h0  (8-k chunks, 2 h/lane) ===============
        {
            const float* pz = wz1t + ch * 16 * 129;
            const float* phl = h0Lo + ch * 16 * 4;
            const float* phh = h0Hi + ch * 16 * 4;
            #pragma unroll 8
            for (int kk = 0; kk < 16; kk++) {
                u64 wA = dup2(pz[kk * 129 + hA]);
                u64 wB = dup2(pz[kk * 129 + hB]);
                ulonglong2 hl = *(const ulonglong2*)(phl + kk * 4);
                ulonglong2 hh2 = *(const ulonglong2*)(phh + kk * 4);
                S0=fma2(wA,hl.x,S0); S1=fma2(wA,hl.y,S1);
                S2=fma2(wA,hh2.x,S2); S3=fma2(wA,hh2.y,S3);
                S4=fma2(wB,hl.x,S4); S5=fma2(wB,hl.y,S5);
                S6=fma2(wB,hh2.x,S6); S7=fma2(wB,hh2.y,S7);
            }
        }
        *(ulonglong2*)(rLo + ch * 512 + hA * 4) = make_ulonglong2(S0, S1);
        *(ulonglong2*)(rHi + ch * 512 + hA * 4) = make_ulonglong2(S2, S3);
        *(ulonglong2*)(rLo + ch * 512 + hB * 4) = make_ulonglong2(S4, S5);
        *(ulonglong2*)(rHi + ch * 512 + hB * 4) = make_ulonglong2(S6, S7);
        __syncthreads();

        // ---- combine B (f32x2): d1' = wz2*sg1 (sg2 deferred); s2 partials -
        {
            const float2* rp = (const float2*)(half ? rHi : rLo);
            float2 s = rp[idx];
            #pragma unroll
            for (int p = 1; p < 8; p++) s = add2(s, rp[p * 256 + idx]);
            float bv = by1v[hQ];
            float h1x, h1y, sg1x, sg1y;
            act2(s.x + bv, h1x, sg1x);
            act2(s.y + bv, h1y, sg1y);
            float wz2h = wz2v[hQ];
            ((float2*)(half ? d1Hi : d1Lo))[idx] =
                make_float2(wz2h * sg1x, wz2h * sg1y);
            float s2x = wz2h * h1x, s2y = wz2h * h1y;
            #pragma unroll
            for (int o = 2; o < 32; o <<= 1) {
                s2x += __shfl_xor_sync(0xffffffffu, s2x, o);
                s2y += __shfl_xor_sync(0xffffffffu, s2y, o);
            }
            if (l < 2) {
                float* sp = half ? s2pH : s2pL;
                ((float2*)(sp + wl * 4))[prQ] = make_float2(s2x, s2y);
            }
        }
        __syncthreads();

        // ---- sg2 finalize (8 threads, overlaps stage C) -------------------
        if (tid < 8) {
            const float* sp = (tid & 4) ? s2pH : s2pL;
            int rr = tid & 3;
            float s2t = 0.0f;
            #pragma unroll
            for (int w = 0; w < 8; w++) s2t += sp[w * 4 + rr];
            float e = __expf(-(s2t + wy2x[tid] + by2v));
            sg2s[tid] = __fdividef(1.0f, 1.0f + e);
        }

        // ===== stage C: Wz1c^T d1' (8-j chunks, 2 k/lane) ==================
        {
            u64 C0=0,C1=0,C2=0,C3=0,C4=0,C5=0,C6=0,C7=0;
            const float* pzA = wz1t + hA * 129 + ch * 16;
            const float* pzB = wz1t + hB * 129 + ch * 16;
            const float* pdl = d1Lo + ch * 16 * 4;
            const float* pdh = d1Hi + ch * 16 * 4;
            #pragma unroll 8
            for (int jj = 0; jj < 16; jj++) {
                u64 wA = dup2(pzA[jj]);
                u64 wB = dup2(pzB[jj]);
                ulonglong2 dl = *(const ulonglong2*)(pdl + jj * 4);
                ulonglong2 dh = *(const ulonglong2*)(pdh + jj * 4);
                C0=fma2(wA,dl.x,C0); C1=fma2(wA,dl.y,C1);
                C2=fma2(wA,dh.x,C2); C3=fma2(wA,dh.y,C3);
                C4=fma2(wB,dl.x,C4); C5=fma2(wB,dl.y,C5);
                C6=fma2(wB,dh.x,C6); C7=fma2(wB,dh.y,C7);
            }
            *(ulonglong2*)(rLo + ch * 512 + hA * 4) = make_ulonglong2(C0, C1);
            *(ulonglong2*)(rHi + ch * 512 + hA * 4) = make_ulonglong2(C2, C3);
            *(ulonglong2*)(rLo + ch * 512 + hB * 4) = make_ulonglong2(C4, C5);
            *(ulonglong2*)(rHi + ch * 512 + hB * 4) = make_ulonglong2(C6, C7);
        }
        __syncthreads();

        // ---- combine C (f32x2): d0' = sg0 * sum ---------------------------
        {
            const float2* rp = (const float2*)(half ? rHi : rLo);
            float2 c2 = rp[idx];
            #pragma unroll
            for (int p = 1; p < 8; p++) c2 = add2(c2, rp[p * 256 + idx]);
            ((float2*)(half ? d0Hi : d0Lo))[idx] =
                make_float2(sg0_0 * c2.x, sg0_1 * c2.y);
        }
        __syncthreads();

        // ===== stage D: Wy1^T d1' + Wy0^T d0' (16 h-chunks, 2 c/lane) ======
        {
            u64 G0=0,G1=0,G2=0,G3=0,G4=0,G5=0,G6=0,G7=0;
            const float* p1A = wy1t + cA * 129 + warp * 8;
            const float* p1B = wy1t + cB * 129 + warp * 8;
            const float* p0A = wy0t + cA * 129 + warp * 8;
            const float* p0B = wy0t + cB * 129 + warp * 8;
            const float* q1l = d1Lo + warp * 8 * 4;
            const float* q1h = d1Hi + warp * 8 * 4;
            const float* q0l = d0Lo + warp * 8 * 4;
            const float* q0h = d0Hi + warp * 8 * 4;
            #pragma unroll
            for (int h2 = 0; h2 < 8; h2++) {
                u64 w1A = dup2(p1A[h2]);
                u64 w1B = dup2(p1B[h2]);
                u64 w0A = dup2(p0A[h2]);
                u64 w0B = dup2(p0B[h2]);
                ulonglong2 al = *(const ulonglong2*)(q1l + h2 * 4);
                ulonglong2 ah = *(const ulonglong2*)(q1h + h2 * 4);
                ulonglong2 bl = *(const ulonglong2*)(q0l + h2 * 4);
                ulonglong2 bh = *(const ulonglong2*)(q0h + h2 * 4);
                G0=fma2(w1A,al.x,G0); G1=fma2(w1A,al.y,G1);
                G2=fma2(w1A,ah.x,G2); G3=fma2(w1A,ah.y,G3);
                G0=fma2(w0A,bl.x,G0); G1=fma2(w0A,bl.y,G1);
                G2=fma2(w0A,bh.x,G2); G3=fma2(w0A,bh.y,G3);
                G4=fma2(w1B,al.x,G4); G5=fma2(w1B,al.y,G5);
                G6=fma2(w1B,ah.x,G6); G7=fma2(w1B,ah.y,G7);
                G4=fma2(w0B,bl.x,G4); G5=fma2(w0B,bl.y,G5);
                G6=fma2(w0B,bh.x,G6); G7=fma2(w0B,bh.y,G7);
            }
            *(ulonglong2*)(rLo + warp * 256 + cA * 4) = make_ulonglong2(G0, G1);
            *(ulonglong2*)(rHi + warp * 256 + cA * 4) = make_ulonglong2(G2, G3);
            *(ulonglong2*)(rLo + warp * 256 + cB * 4) = make_ulonglong2(G4, G5);
            *(ulonglong2*)(rHi + warp * 256 + cB * 4) = make_ulonglong2(G6, G7);
        }
        __syncthreads();

        // ---- combine D (256 threads, f32x2): residual + update + partials -
        if (tid < 256) {
            const float2* rp = (const float2*)(halfD ? rHi : rLo);
            float2 gs = rp[idx2];
            #pragma unroll
            for (int p = 1; p < 16; p++) gs = add2(gs, rp[p * 128 + idx2]);
            float* xX  = halfD ? xHi : xLo;
            float* xoX = halfD ? xoHi : xoLo;
            const float* zX = halfD ? zHi : zLo;
            float2 sg2p = ((const float2*)sg2s)[halfD * 2 + prD];
            float wy2c = wy2v[cQ];
            float2 xc = ((const float2*)xX)[idx2];
            float2 zz = ((const float2*)zX)[idx2];
            float gfx = fmaf(sg2p.x, gs.x + wy2c, xc.x);
            float gfy = fmaf(sg2p.y, gs.y + wy2c, xc.y);
            float rvx = zz.x - gfx, rvy = zz.y - gfy;
            float nnx = rvx * rvx, nny = rvy * rvy;
            float lr = 2.0f / ((float)it + 1.0f);
            float xnx = fmaf(lr, rvx, xc.x), xny = fmaf(lr, rvy, xc.y);
            ((float2*)xoX)[idx2] = xc;
            ((float2*)xX)[idx2]  = make_float2(xnx, xny);
            float p2x = wy2c * xnx, p2y = wy2c * xny;
            #pragma unroll
            for (int o = 2; o < 32; o <<= 1) {
                nnx += __shfl_xor_sync(0xffffffffu, nnx, o);
                nny += __shfl_xor_sync(0xffffffffu, nny, o);
                p2x += __shfl_xor_sync(0xffffffffu, p2x, o);
                p2y += __shfl_xor_sync(0xffffffffu, p2y, o);
            }
            if (l < 2) {
                ((float2*)(nrmp + warp * 4))[prD] = make_float2(nnx, nny);
                ((float2*)(wyp  + warp * 4))[prD] = make_float2(p2x, p2y);
            }
        }
        __syncthreads();

        // ---- convergence ---------------------------------------------------
        if (tid < 8) {
            int wb = (tid >> 2) * 4, rr = tid & 3;   // Lo: warps 0-3, Hi: 4-7
            float nr = 0.0f, ws = 0.0f;
            #pragma unroll
            for (int w = 0; w < 4; w++) {
                nr += nrmp[(wb + w) * 4 + rr];
                ws += wyp[(wb + w) * 4 + rr];
            }
            wy2x[tid] = ws;
            float s = sqrtf(nr);
            s += __shfl_xor_sync(0xffu, s, 4, 8);
            s += __shfl_xor_sync(0xffu, s, 2, 8);
            s += __shfl_xor_sync(0xffu, s, 1, 8);
            if (tid == 0) {
                atomicAdd(&g_stat[it],
                          (1ULL << CNT_SHIFT) +
                          (u64)((double)s * 4294967296.0));
                int dn = 0;
                if (it > 0) {
                    while ((vstat >> CNT_SHIFT) < NUNITS) {
                        asm volatile("ld.global.cg.u64 %0, [%1];"
                                     : "=l"(vstat) : "l"(g_stat + (it - 1)));
                    }
                    dn = (vstat & ERR_MASK) < ERR_THRESH;
                }
                *flagI = dn;
            }
        }
        __syncthreads();
        if (*flagI) { fin = true; break; }
    }

    if (tid < 256) {
        const float* xX = fin ? (halfD ? xoHi : xoLo) : (halfD ? xHi : xLo);
        const float* zX = halfD ? zHi : zLo;
        int rbase = r0 + halfD * 4 + prD * 2;
        out[rbase * 64 + cQ]       = xX[idx2 * 2]     + zX[idx2 * 2];
        out[(rbase + 1) * 64 + cQ] = xX[idx2 * 2 + 1] + zX[idx2 * 2 + 1];
    }
}

extern "C" void kernel_launch(void* const* d_in, const int* in_sizes, int n_in,
                              void* d_out, int out_size) {
    const float* x   = (const float*)d_in[0];
    const float* Wy0 = (const float*)d_in[1];
    const float* by0 = (const float*)d_in[2];
    const float* Wy1 = (const float*)d_in[3];
    const float* by1 = (const float*)d_in[4];
    const float* Wz1 = (const float*)d_in[5];
    const float* Wy2 = (const float*)d_in[6];
    const float* by2 = (const float*)d_in[7];
    const float* Wz2 = (const float*)d_in[8];
    float* out = (float*)d_out;

    static bool attr_set = false;
    if (!attr_set) {
        cudaFuncSetAttribute(blnn_main_kernel,
                             cudaFuncAttributeMaxDynamicSharedMemorySize,
                             SMEM_BYTES);
        attr_set = true;
    }

    blnn_init_kernel<<<1, 512>>>();
    blnn_main_kernel<<<NCTA, THREADS, SMEM_BYTES>>>(x, Wy0, by0, Wy1, by1, Wz1,
                                                    Wy2, by2, Wz2, out);
}

// round 9
// speedup vs baseline: 3.1720x; 1.3267x over previous
#include <cuda_runtime.h>
#include <cstdint>

// ---------------------------------------------------------------------------
// BLNN round 9: R8 + convergence protocol folded into the stage-A segment.
//  err(it-1) is posted BEFORE GEMV-A, spun-on AFTER it (latency hidden under
//  ~3K cycles of GEMV work); flag known before combine-D so the gated update
//  is simply skipped -> no rollback buffers. 8 barriers/iter (was 9).
// ---------------------------------------------------------------------------

#define NCTA      128
#define THREADS   512
#define NUNITS    128ULL
#define MAX_IT    500
#define CNT_SHIFT 52
#define ERR_MASK  ((1ULL << 52) - 1)
#define ERR_THRESH 4398046511ULL   // 0.001*1024*2^32

typedef unsigned long long u64;

__device__ u64 g_stat[MAX_IT];

__global__ void blnn_init_kernel() {
    int i = blockIdx.x * blockDim.x + threadIdx.x;
    if (i < MAX_IT) g_stat[i] = 0ULL;
}

__device__ __forceinline__ u64 dup2(float w) {
    u64 r; asm("mov.b64 %0,{%1,%1};" : "=l"(r) : "f"(w)); return r;
}
__device__ __forceinline__ u64 fma2(u64 a, u64 b, u64 c) {
    u64 d; asm("fma.rn.f32x2 %0,%1,%2,%3;" : "=l"(d) : "l"(a), "l"(b), "l"(c));
    return d;
}
__device__ __forceinline__ float2 add2(float2 a, float2 b) {
    return make_float2(a.x + b.x, a.y + b.y);
}
__device__ __forceinline__ void act2(float a, float& sp, float& sg) {
    float e = __expf(-fabsf(a));
    float u = 1.0f + e;
    float r = __fdividef(1.0f, u);
    sp = fmaxf(a, 0.0f) + __logf(u);
    sg = (a >= 0.0f) ? r : e * r;
}

// ---- shared layout (float offsets; all 16B-aligned where needed) ----
#define OFF_WZ1T  0
#define OFF_WY0T  16512
#define OFF_WY1T  24768
#define OFF_WY2V  33024
#define OFF_WZ2V  33088
#define OFF_BY0V  33216
#define OFF_BY1V  33344
#define OFF_XLO   33472
#define OFF_XHI   33728
#define OFF_ZLO   33984
#define OFF_ZHI   34240
#define OFF_H0LO  34496
#define OFF_H0HI  35008
#define OFF_D1LO  35520
#define OFF_D1HI  36032
#define OFF_D0LO  36544
#define OFF_D0HI  37056
#define OFF_RLO   37568   // 4096
#define OFF_RHI   41664   // 4096
#define OFF_S2PL  45760   // 32
#define OFF_S2PH  45792   // 32
#define OFF_SG2S  45824   // 8
#define OFF_NRMP  45832   // 32
#define OFF_WYP   45864   // 32
#define OFF_WY2X  45896   // 8
#define OFF_MISC  45904   // 8
#define SMEM_FLOATS 45912
#define SMEM_BYTES  (SMEM_FLOATS * 4)

__global__ void __launch_bounds__(THREADS, 1)
blnn_main_kernel(const float* __restrict__ x_in,
                 const float* __restrict__ Wy0, const float* __restrict__ by0,
                 const float* __restrict__ Wy1, const float* __restrict__ by1,
                 const float* __restrict__ Wz1,
                 const float* __restrict__ Wy2, const float* __restrict__ by2,
                 const float* __restrict__ Wz2,
                 float* __restrict__ out)
{
    extern __shared__ float sm[];
    float* wz1t = sm + OFF_WZ1T;
    float* wy0t = sm + OFF_WY0T;
    float* wy1t = sm + OFF_WY1T;
    float* wy2v = sm + OFF_WY2V;
    float* wz2v = sm + OFF_WZ2V;
    float* by0v = sm + OFF_BY0V;
    float* by1v = sm + OFF_BY1V;
    float* xLo  = sm + OFF_XLO;   float* xHi  = sm + OFF_XHI;
    float* zLo  = sm + OFF_ZLO;   float* zHi  = sm + OFF_ZHI;
    float* h0Lo = sm + OFF_H0LO;  float* h0Hi = sm + OFF_H0HI;
    float* d1Lo = sm + OFF_D1LO;  float* d1Hi = sm + OFF_D1HI;
    float* d0Lo = sm + OFF_D0LO;  float* d0Hi = sm + OFF_D0HI;
    float* rLo  = sm + OFF_RLO;   float* rHi  = sm + OFF_RHI;
    float* s2pL = sm + OFF_S2PL;  float* s2pH = sm + OFF_S2PH;
    float* sg2s = sm + OFF_SG2S;
    float* nrmp = sm + OFF_NRMP;  float* wyp  = sm + OFF_WYP;
    float* wy2x = sm + OFF_WY2X;  float* misc = sm + OFF_MISC;
    volatile int* flagI = (volatile int*)(misc + 1);

    const int tid  = threadIdx.x;
    const int l    = tid & 31;
    const int warp = tid >> 5;
    // GEMV A/B/C mapping
    const int g    = warp & 1;        // h-group
    const int ch   = warp >> 1;       // contraction chunk 0..7
    const int hA   = g * 64 + l;
    const int hB   = hA + 32;
    const int cA   = l, cB = l + 32;  // stage D owned c
    // combine A/B/C mapping: (half, h, rl-pair)
    const int half = tid >> 8;        // 0 Lo, 1 Hi
    const int idx  = tid & 255;       // = 2*h + pr
    const int hQ   = idx >> 1;
    const int prQ  = idx & 1;
    const int wl   = warp & 7;        // warp-in-half
    // combine D mapping (tid < 256): (halfD, c, pr)
    const int halfD = tid >> 7;
    const int idx2  = tid & 127;      // = 2*c + pr
    const int cQ    = idx2 >> 1;
    const int prD   = idx2 & 1;

    // ---- one-time staging ----
    for (int i2 = tid; i2 < 128 * 128; i2 += THREADS) {
        int j = i2 >> 7, k = i2 & 127;
        wz1t[k * 129 + j] = fmaxf(Wz1[i2], 0.0f);
    }
    for (int i2 = tid; i2 < 64 * 128; i2 += THREADS) {
        int cc = i2 >> 7, h = i2 & 127;
        wy0t[cc * 129 + h] = Wy0[h * 64 + cc];
        wy1t[cc * 129 + h] = Wy1[h * 64 + cc];
    }
    if (tid < 64)  wy2v[tid] = Wy2[tid];
    if (tid < 128) {
        wz2v[tid] = fmaxf(Wz2[tid], 0.0f);
        by0v[tid] = by0[tid];
        by1v[tid] = by1[tid];
    }
    const int r0 = blockIdx.x * 8;
    {   // x buffers [c*4 + rl]; rows 0-3 Lo, 4-7 Hi
        int cc = tid >> 3, rr = tid & 7;
        float zv = x_in[(r0 + rr) * 64 + cc];
        if (rr < 4) { zLo[cc * 4 + rr] = zv; xLo[cc * 4 + rr] = 1.0f; }
        else        { zHi[cc * 4 + rr - 4] = zv; xHi[cc * 4 + rr - 4] = 1.0f; }
    }
    if (tid == 0) { misc[0] = by2[0]; *flagI = 0; }
    __syncthreads();
    if (tid == 0) {
        float s = 0.0f;
        for (int i2 = 0; i2 < 64; i2++) s += wy2v[i2];
        #pragma unroll
        for (int r = 0; r < 8; r++) wy2x[r] = s;   // x = 1 initially
    }
    __syncthreads();

    const float by2v = misc[0];

    #pragma unroll 1
    for (int it = 0; it < MAX_IT; ++it) {
        // ---- conv part 1 (before GEMV A): reduce it-1 partials, post err --
        if (tid < 8 && it > 0) {
            int wb = (tid >> 2) * 4, rr = tid & 3;
            float nr = 0.0f, ws = 0.0f;
            #pragma unroll
            for (int w = 0; w < 4; w++) {
                nr += nrmp[(wb + w) * 4 + rr];
                ws += wyp[(wb + w) * 4 + rr];
            }
            wy2x[tid] = ws;
            float s = sqrtf(nr);
            s += __shfl_xor_sync(0xffu, s, 4, 8);
            s += __shfl_xor_sync(0xffu, s, 2, 8);
            s += __shfl_xor_sync(0xffu, s, 1, 8);
            if (tid == 0)
                atomicAdd(&g_stat[it - 1],
                          (1ULL << CNT_SHIFT) +
                          (u64)((double)s * 4294967296.0));
        }

        // ===== stage A: A = Wy0 x ; S = Wy1 x  (8-c chunks, 2 h/lane) ======
        u64 S0=0,S1=0,S2=0,S3=0,S4=0,S5=0,S6=0,S7=0;
        {
            u64 A0=0,A1=0,A2=0,A3=0,A4=0,A5=0,A6=0,A7=0;
            const float* p0 = wy0t + ch * 8 * 129;
            const float* p1 = wy1t + ch * 8 * 129;
            const float* pxl = xLo + ch * 8 * 4;
            const float* pxh = xHi + ch * 8 * 4;
            #pragma unroll
            for (int cc = 0; cc < 8; cc++) {
                u64 w0A = dup2(p0[cc * 129 + hA]);
                u64 w0B = dup2(p0[cc * 129 + hB]);
                u64 w1A = dup2(p1[cc * 129 + hA]);
                u64 w1B = dup2(p1[cc * 129 + hB]);
                ulonglong2 xl = *(const ulonglong2*)(pxl + cc * 4);
                ulonglong2 xh = *(const ulonglong2*)(pxh + cc * 4);
                A0=fma2(w0A,xl.x,A0); A1=fma2(w0A,xl.y,A1);
                A2=fma2(w0A,xh.x,A2); A3=fma2(w0A,xh.y,A3);
                A4=fma2(w0B,xl.x,A4); A5=fma2(w0B,xl.y,A5);
                A6=fma2(w0B,xh.x,A6); A7=fma2(w0B,xh.y,A7);
                S0=fma2(w1A,xl.x,S0); S1=fma2(w1A,xl.y,S1);
                S2=fma2(w1A,xh.x,S2); S3=fma2(w1A,xh.y,S3);
                S4=fma2(w1B,xl.x,S4); S5=fma2(w1B,xl.y,S5);
                S6=fma2(w1B,xh.x,S6); S7=fma2(w1B,xh.y,S7);
            }
            *(ulonglong2*)(rLo + ch * 512 + hA * 4) = make_ulonglong2(A0, A1);
            *(ulonglong2*)(rHi + ch * 512 + hA * 4) = make_ulonglong2(A2, A3);
            *(ulonglong2*)(rLo + ch * 512 + hB * 4) = make_ulonglong2(A4, A5);
            *(ulonglong2*)(rHi + ch * 512 + hB * 4) = make_ulonglong2(A6, A7);
        }

        // ---- conv part 2 (after GEMV A): spin + decide flag ----------------
        if (tid == 0 && it > 0) {
            u64 vstat;
            do {
                asm volatile("ld.global.cg.u64 %0, [%1];"
                             : "=l"(vstat) : "l"(g_stat + (it - 1)));
            } while ((vstat >> CNT_SHIFT) < NUNITS);
            *flagI = (vstat & ERR_MASK) < ERR_THRESH;
        }
        __syncthreads();
        if (*flagI) break;   // update of it never ran -> xb is final

        // ---- combine A (f32x2): h0 + sg0 (sg0 pair kept in regs) ----------
        float sg0_0, sg0_1;
        {
            const float2* rp = (const float2*)(half ? rHi : rLo);
            float2 a = rp[idx];
            #pragma unroll
            for (int p = 1; p < 8; p++) a = add2(a, rp[p * 256 + idx]);
            float bv = by0v[hQ];
            float h0x, h0y;
            act2(a.x + bv, h0x, sg0_0);
            act2(a.y + bv, h0y, sg0_1);
            ((float2*)(half ? h0Hi : h0Lo))[idx] = make_float2(h0x, h0y);
        }
        __syncthreads();

        // ===== stage B: S += Wz1c h0  (8-k chunks, 2 h/lane) ===============
        {
            const float* pz = wz1t + ch * 16 * 129;
            const float* phl = h0Lo + ch * 16 * 4;
            const float* phh = h0Hi + ch * 16 * 4;
            #pragma unroll 8
            for (int kk = 0; kk < 16; kk++) {
                u64 wA = dup2(pz[kk * 129 + hA]);
                u64 wB = dup2(pz[kk * 129 + hB]);
                ulonglong2 hl = *(const ulonglong2*)(phl + kk * 4);
                ulonglong2 hh2 = *(const ulonglong2*)(phh + kk * 4);
                S0=fma2(wA,hl.x,S0); S1=fma2(wA,hl.y,S1);
                S2=fma2(wA,hh2.x,S2); S3=fma2(wA,hh2.y,S3);
                S4=fma2(wB,hl.x,S4); S5=fma2(wB,hl.y,S5);
                S6=fma2(wB,hh2.x,S6); S7=fma2(wB,hh2.y,S7);
            }
        }
        *(ulonglong2*)(rLo + ch * 512 + hA * 4) = make_ulonglong2(S0, S1);
        *(ulonglong2*)(rHi + ch * 512 + hA * 4) = make_ulonglong2(S2, S3);
        *(ulonglong2*)(rLo + ch * 512 + hB * 4) = make_ulonglong2(S4, S5);
        *(ulonglong2*)(rHi + ch * 512 + hB * 4) = make_ulonglong2(S6, S7);
        __syncthreads();

        // ---- combine B (f32x2): d1' = wz2*sg1 (sg2 deferred); s2 partials -
        {
            const float2* rp = (const float2*)(half ? rHi : rLo);
            float2 s = rp[idx];
            #pragma unroll
            for (int p = 1; p < 8; p++) s = add2(s, rp[p * 256 + idx]);
            float bv = by1v[hQ];
            float h1x, h1y, sg1x, sg1y;
            act2(s.x + bv, h1x, sg1x);
            act2(s.y + bv, h1y, sg1y);
            float wz2h = wz2v[hQ];
            ((float2*)(half ? d1Hi : d1Lo))[idx] =
                make_float2(wz2h * sg1x, wz2h * sg1y);
            float s2x = wz2h * h1x, s2y = wz2h * h1y;
            #pragma unroll
            for (int o = 2; o < 32; o <<= 1) {
                s2x += __shfl_xor_sync(0xffffffffu, s2x, o);
                s2y += __shfl_xor_sync(0xffffffffu, s2y, o);
            }
            if (l < 2) {
                float* sp = half ? s2pH : s2pL;
                ((float2*)(sp + wl * 4))[prQ] = make_float2(s2x, s2y);
            }
        }
        __syncthreads();

        // ---- sg2 finalize (8 threads, overlaps stage C) -------------------
        if (tid < 8) {
            const float* sp = (tid & 4) ? s2pH : s2pL;
            int rr = tid & 3;
            float s2t = 0.0f;
            #pragma unroll
            for (int w = 0; w < 8; w++) s2t += sp[w * 4 + rr];
            float e = __expf(-(s2t + wy2x[tid] + by2v));
            sg2s[tid] = __fdividef(1.0f, 1.0f + e);
        }

        // ===== stage C: Wz1c^T d1' (8-j chunks, 2 k/lane) ==================
        {
            u64 C0=0,C1=0,C2=0,C3=0,C4=0,C5=0,C6=0,C7=0;
            const float* pzA = wz1t + hA * 129 + ch * 16;
            const float* pzB = wz1t + hB * 129 + ch * 16;
            const float* pdl = d1Lo + ch * 16 * 4;
            const float* pdh = d1Hi + ch * 16 * 4;
            #pragma unroll 8
            for (int jj = 0; jj < 16; jj++) {
                u64 wA = dup2(pzA[jj]);
                u64 wB = dup2(pzB[jj]);
                ulonglong2 dl = *(const ulonglong2*)(pdl + jj * 4);
                ulonglong2 dh = *(const ulonglong2*)(pdh + jj * 4);
                C0=fma2(wA,dl.x,C0); C1=fma2(wA,dl.y,C1);
                C2=fma2(wA,dh.x,C2); C3=fma2(wA,dh.y,C3);
                C4=fma2(wB,dl.x,C4); C5=fma2(wB,dl.y,C5);
                C6=fma2(wB,dh.x,C6); C7=fma2(wB,dh.y,C7);
            }
            *(ulonglong2*)(rLo + ch * 512 + hA * 4) = make_ulonglong2(C0, C1);
            *(ulonglong2*)(rHi + ch * 512 + hA * 4) = make_ulonglong2(C2, C3);
            *(ulonglong2*)(rLo + ch * 512 + hB * 4) = make_ulonglong2(C4, C5);
            *(ulonglong2*)(rHi + ch * 512 + hB * 4) = make_ulonglong2(C6, C7);
        }
        __syncthreads();

        // ---- combine C (f32x2): d0' = sg0 * sum ---------------------------
        {
            const float2* rp = (const float2*)(half ? rHi : rLo);
            float2 c2 = rp[idx];
            #pragma unroll
            for (int p = 1; p < 8; p++) c2 = add2(c2, rp[p * 256 + idx]);
            ((float2*)(half ? d0Hi : d0Lo))[idx] =
                make_float2(sg0_0 * c2.x, sg0_1 * c2.y);
        }
        __syncthreads();

        // ===== stage D: Wy1^T d1' + Wy0^T d0' (16 h-chunks, 2 c/lane) ======
        {
            u64 G0=0,G1=0,G2=0,G3=0,G4=0,G5=0,G6=0,G7=0;
            const float* p1A = wy1t + cA * 129 + warp * 8;
            const float* p1B = wy1t + cB * 129 + warp * 8;
            const float* p0A = wy0t + cA * 129 + warp * 8;
            const float* p0B = wy0t + cB * 129 + warp * 8;
            const float* q1l = d1Lo + warp * 8 * 4;
            const float* q1h = d1Hi + warp * 8 * 4;
            const float* q0l = d0Lo + warp * 8 * 4;
            const float* q0h = d0Hi + warp * 8 * 4;
            #pragma unroll
            for (int h2 = 0; h2 < 8; h2++) {
                u64 w1A = dup2(p1A[h2]);
                u64 w1B = dup2(p1B[h2]);
                u64 w0A = dup2(p0A[h2]);
                u64 w0B = dup2(p0B[h2]);
                ulonglong2 al = *(const ulonglong2*)(q1l + h2 * 4);
                ulonglong2 ah = *(const ulonglong2*)(q1h + h2 * 4);
                ulonglong2 bl = *(const ulonglong2*)(q0l + h2 * 4);
                ulonglong2 bh = *(const ulonglong2*)(q0h + h2 * 4);
                G0=fma2(w1A,al.x,G0); G1=fma2(w1A,al.y,G1);
                G2=fma2(w1A,ah.x,G2); G3=fma2(w1A,ah.y,G3);
                G0=fma2(w0A,bl.x,G0); G1=fma2(w0A,bl.y,G1);
                G2=fma2(w0A,bh.x,G2); G3=fma2(w0A,bh.y,G3);
                G4=fma2(w1B,al.x,G4); G5=fma2(w1B,al.y,G5);
                G6=fma2(w1B,ah.x,G6); G7=fma2(w1B,ah.y,G7);
                G4=fma2(w0B,bl.x,G4); G5=fma2(w0B,bl.y,G5);
                G6=fma2(w0B,bh.x,G6); G7=fma2(w0B,bh.y,G7);
            }
            *(ulonglong2*)(rLo + warp * 256 + cA * 4) = make_ulonglong2(G0, G1);
            *(ulonglong2*)(rHi + warp * 256 + cA * 4) = make_ulonglong2(G2, G3);
            *(ulonglong2*)(rLo + warp * 256 + cB * 4) = make_ulonglong2(G4, G5);
            *(ulonglong2*)(rHi + warp * 256 + cB * 4) = make_ulonglong2(G6, G7);
        }
        __syncthreads();

        // ---- combine D (256 threads, f32x2): residual + update + partials -
        if (tid < 256) {
            const float2* rp = (const float2*)(halfD ? rHi : rLo);
            float2 gs = rp[idx2];
            #pragma unroll
            for (int p = 1; p < 16; p++) gs = add2(gs, rp[p * 128 + idx2]);
            float* xX  = halfD ? xHi : xLo;
            const float* zX = halfD ? zHi : zLo;
            float2 sg2p = ((const float2*)sg2s)[halfD * 2 + prD];
            float wy2c = wy2v[cQ];
            float2 xc = ((const float2*)xX)[idx2];
            float2 zz = ((const float2*)zX)[idx2];
            float gfx = fmaf(sg2p.x, gs.x + wy2c, xc.x);
            float gfy = fmaf(sg2p.y, gs.y + wy2c, xc.y);
            float rvx = zz.x - gfx, rvy = zz.y - gfy;
            float nnx = rvx * rvx, nny = rvy * rvy;
            float lr = 2.0f / ((float)it + 1.0f);
            float xnx = fmaf(lr, rvx, xc.x), xny = fmaf(lr, rvy, xc.y);
            ((float2*)xX)[idx2]  = make_float2(xnx, xny);
            float p2x = wy2c * xnx, p2y = wy2c * xny;
            #pragma unroll
            for (int o = 2; o < 32; o <<= 1) {
                nnx += __shfl_xor_sync(0xffffffffu, nnx, o);
                nny += __shfl_xor_sync(0xffffffffu, nny, o);
                p2x += __shfl_xor_sync(0xffffffffu, p2x, o);
                p2y += __shfl_xor_sync(0xffffffffu, p2y, o);
            }
            if (l < 2) {
                ((float2*)(nrmp + warp * 4))[prD] = make_float2(nnx, nny);
                ((float2*)(wyp  + warp * 4))[prD] = make_float2(p2x, p2y);
            }
        }
        __syncthreads();
    }

    if (tid < 256) {
        const float* xX = halfD ? xHi : xLo;
        const float* zX = halfD ? zHi : zLo;
        int rbase = r0 + halfD * 4 + prD * 2;
        out[rbase * 64 + cQ]       = xX[idx2 * 2]     + zX[idx2 * 2];
        out[(rbase + 1) * 64 + cQ] = xX[idx2 * 2 + 1] + zX[idx2 * 2 + 1];
    }
}

extern "C" void kernel_launch(void* const* d_in, const int* in_sizes, int n_in,
                              void* d_out, int out_size) {
    const float* x   = (const float*)d_in[0];
    const float* Wy0 = (const float*)d_in[1];
    const float* by0 = (const float*)d_in[2];
    const float* Wy1 = (const float*)d_in[3];
    const float* by1 = (const float*)d_in[4];
    const float* Wz1 = (const float*)d_in[5];
    const float* Wy2 = (const float*)d_in[6];
    const float* by2 = (const float*)d_in[7];
    const float* Wz2 = (const float*)d_in[8];
    float* out = (float*)d_out;

    static bool attr_set = false;
    if (!attr_set) {
        cudaFuncSetAttribute(blnn_main_kernel,
                             cudaFuncAttributeMaxDynamicSharedMemorySize,
                             SMEM_BYTES);
        attr_set = true;
    }

    blnn_init_kernel<<<1, 512>>>();
    blnn_main_kernel<<<NCTA, THREADS, SMEM_BYTES>>>(x, Wy0, by0, Wy1, by1, Wz1,
                                                    Wy2, by2, Wz2, out);
}